// round 5
// baseline (speedup 1.0000x reference)
#include <cuda_runtime.h>
#include <cuda_bf16.h>
#include <cstdint>
#include <math.h>

// ---------------------------------------------------------------------------
// SpatialTransformer via mma.sync bf16 (HMMA) with hi/lo fp32 split.
// Round 5: 4 warps x (64x64) warp tiles, 128 thr, 2 CTAs/SM, staged prefetch.
// ---------------------------------------------------------------------------

#define B_DIM 4
#define S_DIM 2048
#define C_DIM 1024
#define M_ALL (B_DIM * S_DIM)   // 8192

__device__ float g_Q[M_ALL * C_DIM];
__device__ float g_K[M_ALL * C_DIM];
__device__ float g_Vt[C_DIM * M_ALL];                    // V^T: [C][B*S]
__device__ float g_S[(long long)B_DIM * S_DIM * S_DIM];
__device__ float g_T[M_ALL * C_DIM];

__device__ __forceinline__ uint32_t smem_u32(const void* p) {
    uint32_t a;
    asm("{ .reg .u64 t; cvta.to.shared.u64 t, %1; cvt.u32.u64 %0, t; }"
        : "=r"(a) : "l"(p));
    return a;
}

#define LDMX4(r0, r1, r2, r3, addr) \
    asm volatile("ldmatrix.sync.aligned.m8n8.x4.shared.b16 {%0,%1,%2,%3}, [%4];" \
                 : "=r"(r0), "=r"(r1), "=r"(r2), "=r"(r3) : "r"(addr))
#define MMA16816(d, a, b) \
    asm volatile("mma.sync.aligned.m16n8k16.row.col.f32.bf16.bf16.f32 " \
                 "{%0,%1,%2,%3}, {%4,%5,%6,%7}, {%8,%9}, {%0,%1,%2,%3};" \
                 : "+f"((d)[0]), "+f"((d)[1]), "+f"((d)[2]), "+f"((d)[3]) \
                 : "r"((a)[0]), "r"((a)[1]), "r"((a)[2]), "r"((a)[3]), \
                   "r"((b)[0]), "r"((b)[1]))

// smem tile geometry: 128 rows x 32 k of bf16, padded row stride 40 halves
#define KT        32
#define ROW_H     40
#define TILE_H    (128 * ROW_H)          // halves per tile (5120)
#define STAGE_H   (4 * TILE_H)           // Ah, Al, Bh, Bl
#define SMEM_TOTAL (2 * STAGE_H * 2)     // bytes: 81920

__device__ __forceinline__ void split4(float4 v, uint2& hu, uint2& lu) {
    __nv_bfloat16 h0 = __float2bfloat16(v.x), h1 = __float2bfloat16(v.y);
    __nv_bfloat16 h2 = __float2bfloat16(v.z), h3 = __float2bfloat16(v.w);
    __nv_bfloat16 l0 = __float2bfloat16(v.x - __bfloat162float(h0));
    __nv_bfloat16 l1 = __float2bfloat16(v.y - __bfloat162float(h1));
    __nv_bfloat16 l2 = __float2bfloat16(v.z - __bfloat162float(h2));
    __nv_bfloat16 l3 = __float2bfloat16(v.w - __bfloat162float(h3));
    __nv_bfloat162 hp0, hp1, lp0, lp1;
    hp0.x = h0; hp0.y = h1; hp1.x = h2; hp1.y = h3;
    lp0.x = l0; lp0.y = l1; lp1.x = l2; lp1.y = l3;
    hu = make_uint2(*(uint32_t*)&hp0, *(uint32_t*)&hp1);
    lu = make_uint2(*(uint32_t*)&lp0, *(uint32_t*)&lp1);
}

// ---------------------------------------------------------------------------
// D[M,N] = alpha * A[M,K] @ B[N,K]^T (+bias[n]) (+R). 128x128 tile, 128 thr.
// 4 warps, each 64x64. 2 CTAs/SM.
// ---------------------------------------------------------------------------
template<bool HAS_BIAS, bool HAS_RES, bool STORE_TRANS>
__global__ __launch_bounds__(128, 2)
void gemm_mma(const float* __restrict__ A, const float* __restrict__ Bm,
              const float* __restrict__ bias, const float* __restrict__ Rm,
              float* __restrict__ Cm, int K, float alpha,
              int ldA, int ldB, int ldC,
              long long sA, long long sB, long long sC, long long sR)
{
    extern __shared__ __align__(16) char smem_raw[];
    __nv_bfloat16* sh = reinterpret_cast<__nv_bfloat16*>(smem_raw);
    const uint32_t sm_base = smem_u32(sh);

    const int tid  = threadIdx.x;
    const int wid  = tid >> 5;
    const int lane = tid & 31;
    const int z    = blockIdx.z;
    const int m0   = blockIdx.y * 128;
    const int n0   = blockIdx.x * 128;

    const float* Ag = A  + z * sA + (size_t)m0 * ldA;
    const float* Bg = Bm + z * sB + (size_t)n0 * ldB;

    const int warp_m = (wid & 1) * 64;    // 2 m-warps
    const int warp_n = (wid >> 1) * 64;   // 2 n-warps, 64 cols each

    // gmem load mapping: 64 rows per batch, 2 threads per row
    const int lrow  = tid >> 1;                // 0..63
    const int lkb   = (tid & 1) * 16;
    const int soff  = lrow * ROW_H + lkb;      // batch rb adds 64*ROW_H

    // ldmatrix address components
    const int arow  = warp_m + (lane & 15);
    const int acolr = (lane >> 4) << 3;                        // +0 / +8
    const int brow_off = ((lane >> 4) << 3) + (lane & 7);
    const int bcolr = lane & 8;

    float acc[4][8][4];
#pragma unroll
    for (int i = 0; i < 4; i++)
#pragma unroll
        for (int j = 0; j < 8; j++)
#pragma unroll
            for (int c = 0; c < 4; c++) acc[i][j][c] = 0.f;

    const int NK = K >> 5;

    // ---- fill stage 0 (both row batches of A and B)
    {
        __nv_bfloat16* Ah = sh;                 __nv_bfloat16* Al = sh + TILE_H;
        __nv_bfloat16* Bh = sh + 2 * TILE_H;    __nv_bfloat16* Bl = sh + 3 * TILE_H;
#pragma unroll
        for (int rb = 0; rb < 2; rb++) {
            const int row = lrow + rb * 64;
            const int so  = soff + rb * 64 * ROW_H;
#pragma unroll
            for (int c = 0; c < 4; c++) {
                float4 v = *reinterpret_cast<const float4*>(Ag + (size_t)row * ldA + lkb + c * 4);
                uint2 hu, lu; split4(v, hu, lu);
                *reinterpret_cast<uint2*>(Ah + so + c * 4) = hu;
                *reinterpret_cast<uint2*>(Al + so + c * 4) = lu;
                v = *reinterpret_cast<const float4*>(Bg + (size_t)row * ldB + lkb + c * 4);
                split4(v, hu, lu);
                *reinterpret_cast<uint2*>(Bh + so + c * 4) = hu;
                *reinterpret_cast<uint2*>(Bl + so + c * 4) = lu;
            }
        }
    }
    __syncthreads();

    for (int kt = 0; kt < NK; ++kt) {
        const int buf = kt & 1;
        const bool more = (kt + 1 < NK);
        const uint32_t stg = sm_base + (uint32_t)(buf * STAGE_H) * 2;
        __nv_bfloat16* nb = sh + (buf ^ 1) * STAGE_H;
        const float* Ak = Ag + (size_t)(kt + 1) * KT;
        const float* Bk = Bg + (size_t)(kt + 1) * KT;

        float4 pv[4];
        // prefetch A(kt+1) rows batch 0
        if (more) {
#pragma unroll
            for (int c = 0; c < 4; c++)
                pv[c] = *reinterpret_cast<const float4*>(Ak + (size_t)lrow * ldA + lkb + c * 4);
        }

#pragma unroll
        for (int half = 0; half < 2; ++half) {
            const int kk = half * 16;
            uint32_t af[4][4];         // reused: hi then lo
            uint32_t bh[8][2], bl[8][2];

            // A hi
#pragma unroll
            for (int i = 0; i < 4; i++) {
                const uint32_t byt = (uint32_t)(((arow + i * 16) * ROW_H + kk + acolr) * 2);
                LDMX4(af[i][0], af[i][1], af[i][2], af[i][3], stg + byt);
            }
            // B hi + lo (8 n8 tiles each)
#pragma unroll
            for (int jj = 0; jj < 8; jj += 2) {
                const uint32_t byt =
                    (uint32_t)(((warp_n + jj * 8 + brow_off) * ROW_H + kk + bcolr) * 2);
                LDMX4(bh[jj][0], bh[jj][1], bh[jj + 1][0], bh[jj + 1][1],
                      stg + (uint32_t)(2 * TILE_H * 2) + byt);
                LDMX4(bl[jj][0], bl[jj][1], bl[jj + 1][0], bl[jj + 1][1],
                      stg + (uint32_t)(3 * TILE_H * 2) + byt);
            }

            // pass 1: Ah * Bh
#pragma unroll
            for (int i = 0; i < 4; i++)
#pragma unroll
                for (int j = 0; j < 8; j++)
                    MMA16816(acc[i][j], af[i], bh[j]);

            // slot (half*2): store pv, reload pv
            if (more) {
                if (half == 0) {
                    // store A batch0 -> next buf; load A batch1
#pragma unroll
                    for (int c = 0; c < 4; c++) {
                        uint2 hu, lu; split4(pv[c], hu, lu);
                        *reinterpret_cast<uint2*>(nb + soff + c * 4) = hu;
                        *reinterpret_cast<uint2*>(nb + TILE_H + soff + c * 4) = lu;
                    }
#pragma unroll
                    for (int c = 0; c < 4; c++)
                        pv[c] = *reinterpret_cast<const float4*>(
                            Ak + (size_t)(lrow + 64) * ldA + lkb + c * 4);
                } else {
                    // store B batch0 -> next buf; load B batch1
#pragma unroll
                    for (int c = 0; c < 4; c++) {
                        uint2 hu, lu; split4(pv[c], hu, lu);
                        *reinterpret_cast<uint2*>(nb + 2 * TILE_H + soff + c * 4) = hu;
                        *reinterpret_cast<uint2*>(nb + 3 * TILE_H + soff + c * 4) = lu;
                    }
#pragma unroll
                    for (int c = 0; c < 4; c++)
                        pv[c] = *reinterpret_cast<const float4*>(
                            Bk + (size_t)(lrow + 64) * ldB + lkb + c * 4);
                }
            }

            // pass 2: Ah * Bl
#pragma unroll
            for (int i = 0; i < 4; i++)
#pragma unroll
                for (int j = 0; j < 8; j++)
                    MMA16816(acc[i][j], af[i], bl[j]);

            // A lo into same regs
#pragma unroll
            for (int i = 0; i < 4; i++) {
                const uint32_t byt = (uint32_t)(((arow + i * 16) * ROW_H + kk + acolr) * 2);
                LDMX4(af[i][0], af[i][1], af[i][2], af[i][3],
                      stg + (uint32_t)(TILE_H * 2) + byt);
            }
            // pass 3: Al * Bh
#pragma unroll
            for (int i = 0; i < 4; i++)
#pragma unroll
                for (int j = 0; j < 8; j++)
                    MMA16816(acc[i][j], af[i], bh[j]);

            // slot (half*2+1): store pv, reload pv
            if (more) {
                if (half == 0) {
                    // store A batch1; load B batch0
#pragma unroll
                    for (int c = 0; c < 4; c++) {
                        uint2 hu, lu; split4(pv[c], hu, lu);
                        *reinterpret_cast<uint2*>(nb + 64 * ROW_H + soff + c * 4) = hu;
                        *reinterpret_cast<uint2*>(nb + TILE_H + 64 * ROW_H + soff + c * 4) = lu;
                    }
#pragma unroll
                    for (int c = 0; c < 4; c++)
                        pv[c] = *reinterpret_cast<const float4*>(
                            Bk + (size_t)lrow * ldB + lkb + c * 4);
                } else {
                    // store B batch1
#pragma unroll
                    for (int c = 0; c < 4; c++) {
                        uint2 hu, lu; split4(pv[c], hu, lu);
                        *reinterpret_cast<uint2*>(nb + 2 * TILE_H + 64 * ROW_H + soff + c * 4) = hu;
                        *reinterpret_cast<uint2*>(nb + 3 * TILE_H + 64 * ROW_H + soff + c * 4) = lu;
                    }
                }
            }
        }
        __syncthreads();
    }

    // epilogue
    const int gq = lane >> 2;        // 0..7
    const int tq = lane & 3;         // 0..3
#pragma unroll
    for (int i = 0; i < 4; i++) {
#pragma unroll
        for (int j = 0; j < 8; j++) {
            const int col = n0 + warp_n + j * 8 + tq * 2;
#pragma unroll
            for (int h = 0; h < 2; h++) {
                const int row = m0 + warp_m + i * 16 + gq + h * 8;
                float v0 = acc[i][j][2 * h]     * alpha;
                float v1 = acc[i][j][2 * h + 1] * alpha;
                if (HAS_BIAS) {
                    float2 bb = *reinterpret_cast<const float2*>(bias + col);
                    v0 += bb.x; v1 += bb.y;
                }
                if (STORE_TRANS) {
                    Cm[z * sC + (size_t)col * ldC + row]       = v0;
                    Cm[z * sC + (size_t)(col + 1) * ldC + row] = v1;
                } else {
                    float* op = Cm + z * sC + (size_t)row * ldC + col;
                    if (HAS_RES) {
                        float2 r = *reinterpret_cast<const float2*>(
                            Rm + z * sR + (size_t)row * ldC + col);
                        v0 += r.x; v1 += r.y;
                    }
                    *reinterpret_cast<float2*>(op) = make_float2(v0, v1);
                }
            }
        }
    }
}

// ---------------------------------------------------------------------------
__global__ __launch_bounds__(256)
void softmax2048(float* __restrict__ S)
{
    const long long row = blockIdx.x;
    float* p = S + row * 2048;
    const int tid = threadIdx.x;
    const int w = tid >> 5, l = tid & 31;

    float v[8];
    {
        float4 x0 = *reinterpret_cast<const float4*>(p + tid * 8);
        float4 x1 = *reinterpret_cast<const float4*>(p + tid * 8 + 4);
        v[0] = x0.x; v[1] = x0.y; v[2] = x0.z; v[3] = x0.w;
        v[4] = x1.x; v[5] = x1.y; v[6] = x1.z; v[7] = x1.w;
    }
    __shared__ float smax[8], ssum[8];

    float m = v[0];
#pragma unroll
    for (int j = 1; j < 8; j++) m = fmaxf(m, v[j]);
#pragma unroll
    for (int off = 16; off >= 1; off >>= 1)
        m = fmaxf(m, __shfl_xor_sync(0xffffffffu, m, off));
    if (l == 0) smax[w] = m;
    __syncthreads();
    float bm = smax[0];
#pragma unroll
    for (int j = 1; j < 8; j++) bm = fmaxf(bm, smax[j]);

    float s = 0.f;
#pragma unroll
    for (int j = 0; j < 8; j++) { v[j] = expf(v[j] - bm); s += v[j]; }
#pragma unroll
    for (int off = 16; off >= 1; off >>= 1)
        s += __shfl_xor_sync(0xffffffffu, s, off);
    if (l == 0) ssum[w] = s;
    __syncthreads();
    float tot = ssum[0];
#pragma unroll
    for (int j = 1; j < 8; j++) tot += ssum[j];

    const float inv = 1.f / tot;
#pragma unroll
    for (int j = 0; j < 8; j++) v[j] *= inv;
    *reinterpret_cast<float4*>(p + tid * 8)     = make_float4(v[0], v[1], v[2], v[3]);
    *reinterpret_cast<float4*>(p + tid * 8 + 4) = make_float4(v[4], v[5], v[6], v[7]);
}

// ---------------------------------------------------------------------------
extern "C" void kernel_launch(void* const* d_in, const int* in_sizes, int n_in,
                              void* d_out, int out_size)
{
    (void)in_sizes; (void)n_in; (void)out_size;
    const float* x  = (const float*)d_in[0];
    const float* ce = (const float*)d_in[1];
    const float* Wq = (const float*)d_in[2];
    const float* bq = (const float*)d_in[3];
    const float* Wk = (const float*)d_in[4];
    const float* bk = (const float*)d_in[5];
    const float* Wv = (const float*)d_in[6];
    const float* bv = (const float*)d_in[7];
    const float* Wo = (const float*)d_in[8];
    const float* bo = (const float*)d_in[9];
    float* out = (float*)d_out;

    float *Q, *K, *Vt, *S, *T;
    cudaGetSymbolAddress((void**)&Q,  g_Q);
    cudaGetSymbolAddress((void**)&K,  g_K);
    cudaGetSymbolAddress((void**)&Vt, g_Vt);
    cudaGetSymbolAddress((void**)&S,  g_S);
    cudaGetSymbolAddress((void**)&T,  g_T);

    cudaFuncSetAttribute(gemm_mma<true,  false, false>, cudaFuncAttributeMaxDynamicSharedMemorySize, SMEM_TOTAL);
    cudaFuncSetAttribute(gemm_mma<true,  false, true >, cudaFuncAttributeMaxDynamicSharedMemorySize, SMEM_TOTAL);
    cudaFuncSetAttribute(gemm_mma<false, false, false>, cudaFuncAttributeMaxDynamicSharedMemorySize, SMEM_TOTAL);
    cudaFuncSetAttribute(gemm_mma<false, true,  false>, cudaFuncAttributeMaxDynamicSharedMemorySize, SMEM_TOTAL);

    const long long sQ = (long long)S_DIM * C_DIM;
    const long long sS = (long long)S_DIM * S_DIM;

    // Q/K projections: [8192,1024] = in @ W^T + b
    gemm_mma<true, false, false><<<dim3(8, 64, 1), 128, SMEM_TOTAL>>>(
        x,  Wq, bq, nullptr, Q, C_DIM, 1.f, C_DIM, C_DIM, C_DIM, 0, 0, 0, 0);
    gemm_mma<true, false, false><<<dim3(8, 64, 1), 128, SMEM_TOTAL>>>(
        ce, Wk, bk, nullptr, K, C_DIM, 1.f, C_DIM, C_DIM, C_DIM, 0, 0, 0, 0);
    // V projection stored transposed: Vt[ch][b*2048+tok], ldC = M_ALL
    gemm_mma<true, false, true><<<dim3(8, 64, 1), 128, SMEM_TOTAL>>>(
        ce, Wv, bv, nullptr, Vt, C_DIM, 1.f, C_DIM, C_DIM, M_ALL, 0, 0, 0, 0);

    // scores: per-batch [2048,2048] = Q @ K^T / 32
    gemm_mma<false, false, false><<<dim3(16, 16, B_DIM), 128, SMEM_TOTAL>>>(
        Q, K, nullptr, nullptr, S, C_DIM, 0.03125f, C_DIM, C_DIM, S_DIM, sQ, sQ, sS, 0);

    softmax2048<<<M_ALL, 256>>>(S);

    // attended + residual: T = P @ Vt^T + x (k runs over tokens)
    gemm_mma<false, true, false><<<dim3(8, 16, B_DIM), 128, SMEM_TOTAL>>>(
        S, Vt, nullptr, x, T, S_DIM, 1.f, S_DIM, M_ALL, C_DIM, sS, S_DIM, sQ, sQ);

    // output projection
    gemm_mma<true, false, false><<<dim3(8, 64, 1), 128, SMEM_TOTAL>>>(
        T, Wo, bo, nullptr, out, C_DIM, 1.f, C_DIM, C_DIM, C_DIM, 0, 0, 0, 0);
}

// round 6
// speedup vs baseline: 1.1442x; 1.1442x over previous
#include <cuda_runtime.h>
#include <cuda_bf16.h>
#include <cstdint>
#include <math.h>

// ---------------------------------------------------------------------------
// SpatialTransformer via mma.sync bf16 (HMMA), hi/lo fp32 split.
// Round 6: operands pre-split to planar bf16 hi/lo; GEMM loads via cp.async;
// round-4 geometry (128x128 tile, 8 warps of 64x32, 2 CTAs/SM).
// ---------------------------------------------------------------------------

#define B_DIM 4
#define S_DIM 2048
#define C_DIM 1024
#define M_ALL (B_DIM * S_DIM)   // 8192

typedef __nv_bfloat16 bf16;

// fp32 scratch
__device__ float g_S[(long long)B_DIM * S_DIM * S_DIM];  // scores, 64 MB
// bf16 hi/lo scratch
__device__ bf16 g_xh[M_ALL * C_DIM],  g_xl[M_ALL * C_DIM];
__device__ bf16 g_ceh[M_ALL * C_DIM], g_cel[M_ALL * C_DIM];
__device__ bf16 g_Wqh[C_DIM * C_DIM], g_Wql[C_DIM * C_DIM];
__device__ bf16 g_Wkh[C_DIM * C_DIM], g_Wkl[C_DIM * C_DIM];
__device__ bf16 g_Wvh[C_DIM * C_DIM], g_Wvl[C_DIM * C_DIM];
__device__ bf16 g_Woh[C_DIM * C_DIM], g_Wol[C_DIM * C_DIM];
__device__ bf16 g_Qh[M_ALL * C_DIM],  g_Ql[M_ALL * C_DIM];
__device__ bf16 g_Kh[M_ALL * C_DIM],  g_Kl[M_ALL * C_DIM];
__device__ bf16 g_Vth[C_DIM * M_ALL], g_Vtl[C_DIM * M_ALL];
__device__ bf16 g_Ph[(long long)B_DIM * S_DIM * S_DIM], g_Pl[(long long)B_DIM * S_DIM * S_DIM];
__device__ bf16 g_Th[M_ALL * C_DIM],  g_Tl[M_ALL * C_DIM];

__device__ __forceinline__ uint32_t smem_u32(const void* p) {
    uint32_t a;
    asm("{ .reg .u64 t; cvta.to.shared.u64 t, %1; cvt.u32.u64 %0, t; }"
        : "=r"(a) : "l"(p));
    return a;
}

#define LDMX4(r0, r1, r2, r3, addr) \
    asm volatile("ldmatrix.sync.aligned.m8n8.x4.shared.b16 {%0,%1,%2,%3}, [%4];" \
                 : "=r"(r0), "=r"(r1), "=r"(r2), "=r"(r3) : "r"(addr))
#define MMA16816(d, a, b) \
    asm volatile("mma.sync.aligned.m16n8k16.row.col.f32.bf16.bf16.f32 " \
                 "{%0,%1,%2,%3}, {%4,%5,%6,%7}, {%8,%9}, {%0,%1,%2,%3};" \
                 : "+f"((d)[0]), "+f"((d)[1]), "+f"((d)[2]), "+f"((d)[3]) \
                 : "r"((a)[0]), "r"((a)[1]), "r"((a)[2]), "r"((a)[3]), \
                   "r"((b)[0]), "r"((b)[1]))
#define CP_ASYNC16(dst, src) \
    asm volatile("cp.async.cg.shared.global [%0], [%1], 16;" \
                 :: "r"(dst), "l"(src) : "memory")
#define CP_COMMIT() asm volatile("cp.async.commit_group;" ::: "memory")
#define CP_WAIT0()  asm volatile("cp.async.wait_group 0;" ::: "memory")
#define CP_WAIT1()  asm volatile("cp.async.wait_group 1;" ::: "memory")

// smem tile geometry: 128 rows x 32 k of bf16, padded row stride 40 halves
#define KT        32
#define ROW_H     40
#define TILE_H    (128 * ROW_H)          // halves (5120)
#define STAGE_H   (4 * TILE_H)           // Ah, Al, Bh, Bl
#define SMEM_TOTAL (2 * STAGE_H * 2)     // bytes: 81920

__device__ __forceinline__ uint32_t packbf(bf16 a, bf16 b) {
    __nv_bfloat162 t; t.x = a; t.y = b;
    return *reinterpret_cast<uint32_t*>(&t);
}
__device__ __forceinline__ void split1(float v, bf16& h, bf16& l) {
    h = __float2bfloat16(v);
    l = __float2bfloat16(v - __bfloat162float(h));
}

// ---------------------------------------------------------------------------
// Elementwise pre-split: fp32 -> bf16 hi + bf16 lo (planar). n divisible 1024.
// ---------------------------------------------------------------------------
__global__ __launch_bounds__(256)
void split_kernel(const float4* __restrict__ in, uint2* __restrict__ h,
                  uint2* __restrict__ l)
{
    const int i = blockIdx.x * 256 + threadIdx.x;
    float4 v = in[i];
    bf16 h0, h1, h2, h3, l0, l1, l2, l3;
    split1(v.x, h0, l0); split1(v.y, h1, l1);
    split1(v.z, h2, l2); split1(v.w, h3, l3);
    h[i] = make_uint2(packbf(h0, h1), packbf(h2, h3));
    l[i] = make_uint2(packbf(l0, l1), packbf(l2, l3));
}

// ---------------------------------------------------------------------------
// GEMM: D[M,N] = alpha * A@B^T (+bias) (+R); A,B given as bf16 hi/lo planes.
// OUT_MODE: 0 = fp32 out, 1 = split bf16 hi/lo out, 2 = split transposed out.
// 128x128 block tile, 256 thr, 8 warps of 64x32, 2 CTAs/SM, cp.async pipeline.
// ---------------------------------------------------------------------------
template<int OUT_MODE, bool HAS_BIAS, bool HAS_RES>
__global__ __launch_bounds__(256, 2)
void gemm_bf(const bf16* __restrict__ Ah, const bf16* __restrict__ Al,
             const bf16* __restrict__ Bh, const bf16* __restrict__ Bl,
             const float* __restrict__ bias, const float* __restrict__ Rm,
             float* __restrict__ Cf, bf16* __restrict__ Ch, bf16* __restrict__ Cl,
             int K, float alpha, int ldA, int ldB, int ldC,
             long long sA, long long sB, long long sC, long long sR)
{
    extern __shared__ __align__(16) char smem_raw[];
    const uint32_t sm_base = smem_u32(smem_raw);

    const int tid  = threadIdx.x;
    const int wid  = tid >> 5;
    const int lane = tid & 31;
    const int z    = blockIdx.z;
    const int m0   = blockIdx.y * 128;
    const int n0   = blockIdx.x * 128;

    const bf16* Agh = Ah + z * sA + (size_t)m0 * ldA;
    const bf16* Agl = Al + z * sA + (size_t)m0 * ldA;
    const bf16* Bgh = Bh + z * sB + (size_t)n0 * ldB;
    const bf16* Bgl = Bl + z * sB + (size_t)n0 * ldB;

    const int warp_m = (wid & 1) * 64;
    const int warp_n = (wid >> 1) * 32;

    // cp.async mapping: 256 thr, per tile 128 rows x 4 chunks(16B); 2 rows/thr
    const int r0 = tid >> 2;            // 0..63
    const int kc = (tid & 3) * 8;       // half offset in ktile

    // ldmatrix address components
    const int arow  = warp_m + (lane & 15);
    const int acolr = (lane >> 4) << 3;
    const int brow_off = ((lane >> 4) << 3) + (lane & 7);
    const int bcolr = lane & 8;

    float acc[4][4][4];
#pragma unroll
    for (int i = 0; i < 4; i++)
#pragma unroll
        for (int j = 0; j < 4; j++)
#pragma unroll
            for (int c = 0; c < 4; c++) acc[i][j][c] = 0.f;

    const int NK = K >> 5;

    // stage loader
    auto load_stage = [&](int buf, int kt) {
        const uint32_t sbase = sm_base + (uint32_t)(buf * STAGE_H) * 2;
        const int kk = kt * KT + kc;
#pragma unroll
        for (int rr = 0; rr < 2; rr++) {
            const int row = r0 + rr * 64;
            const uint32_t so = (uint32_t)(row * ROW_H + kc) * 2;
            CP_ASYNC16(sbase + so,                         Agh + (size_t)row * ldA + kk);
            CP_ASYNC16(sbase + (uint32_t)(TILE_H * 2) + so, Agl + (size_t)row * ldA + kk);
            CP_ASYNC16(sbase + (uint32_t)(2 * TILE_H * 2) + so, Bgh + (size_t)row * ldB + kk);
            CP_ASYNC16(sbase + (uint32_t)(3 * TILE_H * 2) + so, Bgl + (size_t)row * ldB + kk);
        }
    };

    load_stage(0, 0);
    CP_COMMIT();

    for (int kt = 0; kt < NK; ++kt) {
        const int buf = kt & 1;
        if (kt + 1 < NK) {
            load_stage(buf ^ 1, kt + 1);
            CP_COMMIT();
            CP_WAIT1();
        } else {
            CP_WAIT0();
        }
        __syncthreads();

        const uint32_t stg = sm_base + (uint32_t)(buf * STAGE_H) * 2;
#pragma unroll
        for (int half = 0; half < 2; ++half) {
            const int kk = half * 16;
            uint32_t af[4][4];         // reused hi then lo
            uint32_t bh[4][2], bl[4][2];

#pragma unroll
            for (int i = 0; i < 4; i++) {
                const uint32_t byt = (uint32_t)(((arow + i * 16) * ROW_H + kk + acolr) * 2);
                LDMX4(af[i][0], af[i][1], af[i][2], af[i][3], stg + byt);
            }
#pragma unroll
            for (int jj = 0; jj < 4; jj += 2) {
                const uint32_t byt =
                    (uint32_t)(((warp_n + jj * 8 + brow_off) * ROW_H + kk + bcolr) * 2);
                LDMX4(bh[jj][0], bh[jj][1], bh[jj + 1][0], bh[jj + 1][1],
                      stg + (uint32_t)(2 * TILE_H * 2) + byt);
                LDMX4(bl[jj][0], bl[jj][1], bl[jj + 1][0], bl[jj + 1][1],
                      stg + (uint32_t)(3 * TILE_H * 2) + byt);
            }
#pragma unroll
            for (int i = 0; i < 4; i++)
#pragma unroll
                for (int j = 0; j < 4; j++) {
                    MMA16816(acc[i][j], af[i], bh[j]);
                    MMA16816(acc[i][j], af[i], bl[j]);
                }
#pragma unroll
            for (int i = 0; i < 4; i++) {
                const uint32_t byt = (uint32_t)(((arow + i * 16) * ROW_H + kk + acolr) * 2);
                LDMX4(af[i][0], af[i][1], af[i][2], af[i][3],
                      stg + (uint32_t)(TILE_H * 2) + byt);
            }
#pragma unroll
            for (int i = 0; i < 4; i++)
#pragma unroll
                for (int j = 0; j < 4; j++)
                    MMA16816(acc[i][j], af[i], bh[j]);
        }
        __syncthreads();
    }

    // epilogue
    const int gq = lane >> 2;
    const int tq = lane & 3;
#pragma unroll
    for (int i = 0; i < 4; i++) {
#pragma unroll
        for (int j = 0; j < 4; j++) {
            const int col = n0 + warp_n + j * 8 + tq * 2;
#pragma unroll
            for (int h = 0; h < 2; h++) {
                const int row = m0 + warp_m + i * 16 + gq + h * 8;
                float v0 = acc[i][j][2 * h]     * alpha;
                float v1 = acc[i][j][2 * h + 1] * alpha;
                if (HAS_BIAS) {
                    float2 bb = *reinterpret_cast<const float2*>(bias + col);
                    v0 += bb.x; v1 += bb.y;
                }
                if (HAS_RES) {
                    float2 r = *reinterpret_cast<const float2*>(
                        Rm + z * sR + (size_t)row * ldC + col);
                    v0 += r.x; v1 += r.y;
                }
                if (OUT_MODE == 0) {
                    *reinterpret_cast<float2*>(Cf + z * sC + (size_t)row * ldC + col)
                        = make_float2(v0, v1);
                } else {
                    bf16 h0, h1, l0, l1;
                    split1(v0, h0, l0); split1(v1, h1, l1);
                    if (OUT_MODE == 1) {
                        const size_t idx = z * sC + (size_t)row * ldC + col;
                        *reinterpret_cast<uint32_t*>(Ch + idx) = packbf(h0, h1);
                        *reinterpret_cast<uint32_t*>(Cl + idx) = packbf(l0, l1);
                    } else {
                        Ch[z * sC + (size_t)col * ldC + row]       = h0;
                        Ch[z * sC + (size_t)(col + 1) * ldC + row] = h1;
                        Cl[z * sC + (size_t)col * ldC + row]       = l0;
                        Cl[z * sC + (size_t)(col + 1) * ldC + row] = l1;
                    }
                }
            }
        }
    }
}

// ---------------------------------------------------------------------------
// Row softmax (2048/row, fp32 in) -> bf16 hi/lo probability planes.
// ---------------------------------------------------------------------------
__global__ __launch_bounds__(256)
void softmax2048(const float* __restrict__ S, bf16* __restrict__ Ph,
                 bf16* __restrict__ Pl)
{
    const long long row = blockIdx.x;
    const float* p = S + row * 2048;
    const int tid = threadIdx.x;
    const int w = tid >> 5, l = tid & 31;

    float v[8];
    {
        float4 x0 = *reinterpret_cast<const float4*>(p + tid * 8);
        float4 x1 = *reinterpret_cast<const float4*>(p + tid * 8 + 4);
        v[0] = x0.x; v[1] = x0.y; v[2] = x0.z; v[3] = x0.w;
        v[4] = x1.x; v[5] = x1.y; v[6] = x1.z; v[7] = x1.w;
    }
    __shared__ float smax[8], ssum[8];

    float m = v[0];
#pragma unroll
    for (int j = 1; j < 8; j++) m = fmaxf(m, v[j]);
#pragma unroll
    for (int off = 16; off >= 1; off >>= 1)
        m = fmaxf(m, __shfl_xor_sync(0xffffffffu, m, off));
    if (l == 0) smax[w] = m;
    __syncthreads();
    float bm = smax[0];
#pragma unroll
    for (int j = 1; j < 8; j++) bm = fmaxf(bm, smax[j]);

    float s = 0.f;
#pragma unroll
    for (int j = 0; j < 8; j++) { v[j] = expf(v[j] - bm); s += v[j]; }
#pragma unroll
    for (int off = 16; off >= 1; off >>= 1)
        s += __shfl_xor_sync(0xffffffffu, s, off);
    if (l == 0) ssum[w] = s;
    __syncthreads();
    float tot = ssum[0];
#pragma unroll
    for (int j = 1; j < 8; j++) tot += ssum[j];

    const float inv = 1.f / tot;
    bf16 hh[8], ll[8];
#pragma unroll
    for (int j = 0; j < 8; j++) { v[j] *= inv; split1(v[j], hh[j], ll[j]); }

    const long long ob = row * 2048 + tid * 8;
    *reinterpret_cast<uint2*>(Ph + ob) =
        make_uint2(packbf(hh[0], hh[1]), packbf(hh[2], hh[3]));
    *reinterpret_cast<uint2*>(Ph + ob + 4) =
        make_uint2(packbf(hh[4], hh[5]), packbf(hh[6], hh[7]));
    *reinterpret_cast<uint2*>(Pl + ob) =
        make_uint2(packbf(ll[0], ll[1]), packbf(ll[2], ll[3]));
    *reinterpret_cast<uint2*>(Pl + ob + 4) =
        make_uint2(packbf(ll[4], ll[5]), packbf(ll[6], ll[7]));
}

// ---------------------------------------------------------------------------
extern "C" void kernel_launch(void* const* d_in, const int* in_sizes, int n_in,
                              void* d_out, int out_size)
{
    (void)in_sizes; (void)n_in; (void)out_size;
    const float* x  = (const float*)d_in[0];
    const float* ce = (const float*)d_in[1];
    const float* Wq = (const float*)d_in[2];
    const float* bq = (const float*)d_in[3];
    const float* Wk = (const float*)d_in[4];
    const float* bk = (const float*)d_in[5];
    const float* Wv = (const float*)d_in[6];
    const float* bv = (const float*)d_in[7];
    const float* Wo = (const float*)d_in[8];
    const float* bo = (const float*)d_in[9];
    float* out = (float*)d_out;

    float* S;
    bf16 *xh, *xl, *ceh, *cel, *Wqh, *Wql, *Wkh, *Wkl, *Wvh, *Wvl, *Woh, *Wol;
    bf16 *Qh, *Ql, *Kh, *Kl, *Vth, *Vtl, *Ph, *Pl, *Th, *Tl;
    cudaGetSymbolAddress((void**)&S,   g_S);
    cudaGetSymbolAddress((void**)&xh,  g_xh);  cudaGetSymbolAddress((void**)&xl,  g_xl);
    cudaGetSymbolAddress((void**)&ceh, g_ceh); cudaGetSymbolAddress((void**)&cel, g_cel);
    cudaGetSymbolAddress((void**)&Wqh, g_Wqh); cudaGetSymbolAddress((void**)&Wql, g_Wql);
    cudaGetSymbolAddress((void**)&Wkh, g_Wkh); cudaGetSymbolAddress((void**)&Wkl, g_Wkl);
    cudaGetSymbolAddress((void**)&Wvh, g_Wvh); cudaGetSymbolAddress((void**)&Wvl, g_Wvl);
    cudaGetSymbolAddress((void**)&Woh, g_Woh); cudaGetSymbolAddress((void**)&Wol, g_Wol);
    cudaGetSymbolAddress((void**)&Qh,  g_Qh);  cudaGetSymbolAddress((void**)&Ql,  g_Ql);
    cudaGetSymbolAddress((void**)&Kh,  g_Kh);  cudaGetSymbolAddress((void**)&Kl,  g_Kl);
    cudaGetSymbolAddress((void**)&Vth, g_Vth); cudaGetSymbolAddress((void**)&Vtl, g_Vtl);
    cudaGetSymbolAddress((void**)&Ph,  g_Ph);  cudaGetSymbolAddress((void**)&Pl,  g_Pl);
    cudaGetSymbolAddress((void**)&Th,  g_Th);  cudaGetSymbolAddress((void**)&Tl,  g_Tl);

    cudaFuncSetAttribute(gemm_bf<1, true,  false>, cudaFuncAttributeMaxDynamicSharedMemorySize, SMEM_TOTAL);
    cudaFuncSetAttribute(gemm_bf<2, true,  false>, cudaFuncAttributeMaxDynamicSharedMemorySize, SMEM_TOTAL);
    cudaFuncSetAttribute(gemm_bf<0, false, false>, cudaFuncAttributeMaxDynamicSharedMemorySize, SMEM_TOTAL);
    cudaFuncSetAttribute(gemm_bf<1, false, true >, cudaFuncAttributeMaxDynamicSharedMemorySize, SMEM_TOTAL);
    cudaFuncSetAttribute(gemm_bf<0, true,  false>, cudaFuncAttributeMaxDynamicSharedMemorySize, SMEM_TOTAL);

    // pre-split inputs (n/1024 blocks of 256 thr, 4 floats/thr)
    split_kernel<<<M_ALL * C_DIM / 1024, 256>>>((const float4*)x,  (uint2*)xh,  (uint2*)xl);
    split_kernel<<<M_ALL * C_DIM / 1024, 256>>>((const float4*)ce, (uint2*)ceh, (uint2*)cel);
    split_kernel<<<C_DIM * C_DIM / 1024, 256>>>((const float4*)Wq, (uint2*)Wqh, (uint2*)Wql);
    split_kernel<<<C_DIM * C_DIM / 1024, 256>>>((const float4*)Wk, (uint2*)Wkh, (uint2*)Wkl);
    split_kernel<<<C_DIM * C_DIM / 1024, 256>>>((const float4*)Wv, (uint2*)Wvh, (uint2*)Wvl);
    split_kernel<<<C_DIM * C_DIM / 1024, 256>>>((const float4*)Wo, (uint2*)Woh, (uint2*)Wol);

    const long long sQ = (long long)S_DIM * C_DIM;
    const long long sS = (long long)S_DIM * S_DIM;

    // Q/K projections -> split bf16
    gemm_bf<1, true, false><<<dim3(8, 64, 1), 256, SMEM_TOTAL>>>(
        xh, xl, Wqh, Wql, bq, nullptr, nullptr, Qh, Ql,
        C_DIM, 1.f, C_DIM, C_DIM, C_DIM, 0, 0, 0, 0);
    gemm_bf<1, true, false><<<dim3(8, 64, 1), 256, SMEM_TOTAL>>>(
        ceh, cel, Wkh, Wkl, bk, nullptr, nullptr, Kh, Kl,
        C_DIM, 1.f, C_DIM, C_DIM, C_DIM, 0, 0, 0, 0);
    // V projection -> transposed split bf16 (Vt[ch][token])
    gemm_bf<2, true, false><<<dim3(8, 64, 1), 256, SMEM_TOTAL>>>(
        ceh, cel, Wvh, Wvl, bv, nullptr, nullptr, Vth, Vtl,
        C_DIM, 1.f, C_DIM, C_DIM, M_ALL, 0, 0, 0, 0);

    // scores: per-batch Q @ K^T / 32 -> fp32 S
    gemm_bf<0, false, false><<<dim3(16, 16, B_DIM), 256, SMEM_TOTAL>>>(
        Qh, Ql, Kh, Kl, nullptr, nullptr, S, nullptr, nullptr,
        C_DIM, 0.03125f, C_DIM, C_DIM, S_DIM, sQ, sQ, sS, 0);

    // softmax -> split bf16 probabilities
    softmax2048<<<M_ALL, 256>>>(S, Ph, Pl);

    // attended + residual -> split bf16 T  (B operand = Vt, batch offset 2048)
    gemm_bf<1, false, true><<<dim3(8, 16, B_DIM), 256, SMEM_TOTAL>>>(
        Ph, Pl, Vth, Vtl, nullptr, x, nullptr, Th, Tl,
        S_DIM, 1.f, S_DIM, M_ALL, C_DIM, sS, S_DIM, sQ, sQ);

    // output projection -> fp32 out
    gemm_bf<0, true, false><<<dim3(8, 64, 1), 256, SMEM_TOTAL>>>(
        Th, Tl, Woh, Wol, bo, nullptr, out, nullptr, nullptr,
        C_DIM, 1.f, C_DIM, C_DIM, C_DIM, 0, 0, 0, 0);
}

// round 7
// speedup vs baseline: 1.1606x; 1.0144x over previous
#include <cuda_runtime.h>
#include <cuda_bf16.h>
#include <cstdint>
#include <math.h>

// ---------------------------------------------------------------------------
// SpatialTransformer via mma.sync bf16 (HMMA), hi/lo fp32 split.
// Round 7: pre-split planar bf16 operands + cp.async (round 6 infra),
// 64x64 warp tiles (4 warps, 128 thr, 2 CTAs/SM), ordered LDSM/MMA overlap.
// ---------------------------------------------------------------------------

#define B_DIM 4
#define S_DIM 2048
#define C_DIM 1024
#define M_ALL (B_DIM * S_DIM)   // 8192

typedef __nv_bfloat16 bf16;

// fp32 scratch
__device__ float g_S[(long long)B_DIM * S_DIM * S_DIM];  // scores, 64 MB
// bf16 hi/lo scratch
__device__ bf16 g_xh[M_ALL * C_DIM],  g_xl[M_ALL * C_DIM];
__device__ bf16 g_ceh[M_ALL * C_DIM], g_cel[M_ALL * C_DIM];
__device__ bf16 g_Wqh[C_DIM * C_DIM], g_Wql[C_DIM * C_DIM];
__device__ bf16 g_Wkh[C_DIM * C_DIM], g_Wkl[C_DIM * C_DIM];
__device__ bf16 g_Wvh[C_DIM * C_DIM], g_Wvl[C_DIM * C_DIM];
__device__ bf16 g_Woh[C_DIM * C_DIM], g_Wol[C_DIM * C_DIM];
__device__ bf16 g_Qh[M_ALL * C_DIM],  g_Ql[M_ALL * C_DIM];
__device__ bf16 g_Kh[M_ALL * C_DIM],  g_Kl[M_ALL * C_DIM];
__device__ bf16 g_Vth[C_DIM * M_ALL], g_Vtl[C_DIM * M_ALL];
__device__ bf16 g_Ph[(long long)B_DIM * S_DIM * S_DIM], g_Pl[(long long)B_DIM * S_DIM * S_DIM];
__device__ bf16 g_Th[M_ALL * C_DIM],  g_Tl[M_ALL * C_DIM];

__device__ __forceinline__ uint32_t smem_u32(const void* p) {
    uint32_t a;
    asm("{ .reg .u64 t; cvta.to.shared.u64 t, %1; cvt.u32.u64 %0, t; }"
        : "=r"(a) : "l"(p));
    return a;
}

#define LDMX4(r0, r1, r2, r3, addr) \
    asm volatile("ldmatrix.sync.aligned.m8n8.x4.shared.b16 {%0,%1,%2,%3}, [%4];" \
                 : "=r"(r0), "=r"(r1), "=r"(r2), "=r"(r3) : "r"(addr))
#define MMA16816(d, a, b) \
    asm volatile("mma.sync.aligned.m16n8k16.row.col.f32.bf16.bf16.f32 " \
                 "{%0,%1,%2,%3}, {%4,%5,%6,%7}, {%8,%9}, {%0,%1,%2,%3};" \
                 : "+f"((d)[0]), "+f"((d)[1]), "+f"((d)[2]), "+f"((d)[3]) \
                 : "r"((a)[0]), "r"((a)[1]), "r"((a)[2]), "r"((a)[3]), \
                   "r"((b)[0]), "r"((b)[1]))
#define CP_ASYNC16(dst, src) \
    asm volatile("cp.async.cg.shared.global [%0], [%1], 16;" \
                 :: "r"(dst), "l"(src) : "memory")
#define CP_COMMIT() asm volatile("cp.async.commit_group;" ::: "memory")
#define CP_WAIT0()  asm volatile("cp.async.wait_group 0;" ::: "memory")
#define CP_WAIT1()  asm volatile("cp.async.wait_group 1;" ::: "memory")

// smem tile geometry: 128 rows x 32 k of bf16, padded row stride 40 halves
#define KT        32
#define ROW_H     40
#define TILE_H    (128 * ROW_H)          // halves (5120)
#define STAGE_H   (4 * TILE_H)           // Ah, Al, Bh, Bl
#define SMEM_TOTAL (2 * STAGE_H * 2)     // bytes: 81920

__device__ __forceinline__ uint32_t packbf(bf16 a, bf16 b) {
    __nv_bfloat162 t; t.x = a; t.y = b;
    return *reinterpret_cast<uint32_t*>(&t);
}
__device__ __forceinline__ void split1(float v, bf16& h, bf16& l) {
    h = __float2bfloat16(v);
    l = __float2bfloat16(v - __bfloat162float(h));
}

// ---------------------------------------------------------------------------
__global__ __launch_bounds__(256)
void split_kernel(const float4* __restrict__ in, uint2* __restrict__ h,
                  uint2* __restrict__ l)
{
    const int i = blockIdx.x * 256 + threadIdx.x;
    float4 v = in[i];
    bf16 h0, h1, h2, h3, l0, l1, l2, l3;
    split1(v.x, h0, l0); split1(v.y, h1, l1);
    split1(v.z, h2, l2); split1(v.w, h3, l3);
    h[i] = make_uint2(packbf(h0, h1), packbf(h2, h3));
    l[i] = make_uint2(packbf(l0, l1), packbf(l2, l3));
}

// ---------------------------------------------------------------------------
// GEMM: D[M,N] = alpha * A@B^T (+bias) (+R); operands planar bf16 hi/lo.
// OUT_MODE: 0 = fp32 out, 1 = split bf16 hi/lo out, 2 = split transposed out.
// 128x128 block, 128 thr, 4 warps of 64x64, 2 CTAs/SM, cp.async 2-stage.
// ---------------------------------------------------------------------------
template<int OUT_MODE, bool HAS_BIAS, bool HAS_RES>
__global__ __launch_bounds__(128, 2)
void gemm_bf(const bf16* __restrict__ Ah, const bf16* __restrict__ Al,
             const bf16* __restrict__ Bh, const bf16* __restrict__ Bl,
             const float* __restrict__ bias, const float* __restrict__ Rm,
             float* __restrict__ Cf, bf16* __restrict__ Ch, bf16* __restrict__ Cl,
             int K, float alpha, int ldA, int ldB, int ldC,
             long long sA, long long sB, long long sC, long long sR)
{
    extern __shared__ __align__(16) char smem_raw[];
    const uint32_t sm_base = smem_u32(smem_raw);

    const int tid  = threadIdx.x;
    const int wid  = tid >> 5;
    const int lane = tid & 31;
    const int z    = blockIdx.z;
    const int m0   = blockIdx.y * 128;
    const int n0   = blockIdx.x * 128;

    const bf16* Agh = Ah + z * sA + (size_t)m0 * ldA;
    const bf16* Agl = Al + z * sA + (size_t)m0 * ldA;
    const bf16* Bgh = Bh + z * sB + (size_t)n0 * ldB;
    const bf16* Bgl = Bl + z * sB + (size_t)n0 * ldB;

    const int warp_m = (wid & 1) * 64;    // 2 m-groups
    const int warp_n = (wid >> 1) * 64;   // 2 n-groups, 64 cols each

    // cp.async mapping: 128 thr; per tile 128 rows x 4 chunks(16B) = 512;
    // each thread does 4 chunks per tile (rows r0, +32, +64, +96).
    const int r0 = tid >> 2;            // 0..31
    const int kc = (tid & 3) * 8;       // bf16 offset in ktile

    // ldmatrix address components
    const int arow  = warp_m + (lane & 15);
    const int acolr = (lane >> 4) << 3;
    const int brow_off = ((lane >> 4) << 3) + (lane & 7);
    const int bcolr = lane & 8;

    float acc[4][8][4];
#pragma unroll
    for (int i = 0; i < 4; i++)
#pragma unroll
        for (int j = 0; j < 8; j++)
#pragma unroll
            for (int c = 0; c < 4; c++) acc[i][j][c] = 0.f;

    const int NK = K >> 5;

    auto load_stage = [&](int buf, int kt) {
        const uint32_t sbase = sm_base + (uint32_t)(buf * STAGE_H) * 2;
        const int kk = kt * KT + kc;
#pragma unroll
        for (int rr = 0; rr < 4; rr++) {
            const int row = r0 + rr * 32;
            const uint32_t so = (uint32_t)(row * ROW_H + kc) * 2;
            CP_ASYNC16(sbase + so,                              Agh + (size_t)row * ldA + kk);
            CP_ASYNC16(sbase + (uint32_t)(TILE_H * 2) + so,     Agl + (size_t)row * ldA + kk);
            CP_ASYNC16(sbase + (uint32_t)(2 * TILE_H * 2) + so, Bgh + (size_t)row * ldB + kk);
            CP_ASYNC16(sbase + (uint32_t)(3 * TILE_H * 2) + so, Bgl + (size_t)row * ldB + kk);
        }
    };

    load_stage(0, 0);
    CP_COMMIT();

    for (int kt = 0; kt < NK; ++kt) {
        const int buf = kt & 1;
        if (kt + 1 < NK) {
            load_stage(buf ^ 1, kt + 1);
            CP_COMMIT();
            CP_WAIT1();
        } else {
            CP_WAIT0();
        }
        __syncthreads();

        const uint32_t stg = sm_base + (uint32_t)(buf * STAGE_H) * 2;
#pragma unroll
        for (int half = 0; half < 2; ++half) {
            const int kk = half * 16;
            uint32_t af[4][4];          // reused: hi then lo
            uint32_t bh[8][2], bl[8][2];

            // A hi + B hi
#pragma unroll
            for (int i = 0; i < 4; i++) {
                const uint32_t byt = (uint32_t)(((arow + i * 16) * ROW_H + kk + acolr) * 2);
                LDMX4(af[i][0], af[i][1], af[i][2], af[i][3], stg + byt);
            }
#pragma unroll
            for (int jj = 0; jj < 8; jj += 2) {
                const uint32_t byt =
                    (uint32_t)(((warp_n + jj * 8 + brow_off) * ROW_H + kk + bcolr) * 2);
                LDMX4(bh[jj][0], bh[jj][1], bh[jj + 1][0], bh[jj + 1][1],
                      stg + (uint32_t)(2 * TILE_H * 2) + byt);
            }
            // pass 1: Ah*Bh
#pragma unroll
            for (int i = 0; i < 4; i++)
#pragma unroll
                for (int j = 0; j < 8; j++)
                    MMA16816(acc[i][j], af[i], bh[j]);

            // B lo LDSM issued under pass-1 tail
#pragma unroll
            for (int jj = 0; jj < 8; jj += 2) {
                const uint32_t byt =
                    (uint32_t)(((warp_n + jj * 8 + brow_off) * ROW_H + kk + bcolr) * 2);
                LDMX4(bl[jj][0], bl[jj][1], bl[jj + 1][0], bl[jj + 1][1],
                      stg + (uint32_t)(3 * TILE_H * 2) + byt);
            }
            // pass 2: Ah*Bl
#pragma unroll
            for (int i = 0; i < 4; i++)
#pragma unroll
                for (int j = 0; j < 8; j++)
                    MMA16816(acc[i][j], af[i], bl[j]);

            // A lo into same regs, issued under pass-2 tail
#pragma unroll
            for (int i = 0; i < 4; i++) {
                const uint32_t byt = (uint32_t)(((arow + i * 16) * ROW_H + kk + acolr) * 2);
                LDMX4(af[i][0], af[i][1], af[i][2], af[i][3],
                      stg + (uint32_t)(TILE_H * 2) + byt);
            }
            // pass 3: Al*Bh
#pragma unroll
            for (int i = 0; i < 4; i++)
#pragma unroll
                for (int j = 0; j < 8; j++)
                    MMA16816(acc[i][j], af[i], bh[j]);
        }
        __syncthreads();
    }

    // epilogue
    const int gq = lane >> 2;
    const int tq = lane & 3;
#pragma unroll
    for (int i = 0; i < 4; i++) {
#pragma unroll
        for (int j = 0; j < 8; j++) {
            const int col = n0 + warp_n + j * 8 + tq * 2;
#pragma unroll
            for (int h = 0; h < 2; h++) {
                const int row = m0 + warp_m + i * 16 + gq + h * 8;
                float v0 = acc[i][j][2 * h]     * alpha;
                float v1 = acc[i][j][2 * h + 1] * alpha;
                if (HAS_BIAS) {
                    float2 bb = *reinterpret_cast<const float2*>(bias + col);
                    v0 += bb.x; v1 += bb.y;
                }
                if (HAS_RES) {
                    float2 r = *reinterpret_cast<const float2*>(
                        Rm + z * sR + (size_t)row * ldC + col);
                    v0 += r.x; v1 += r.y;
                }
                if (OUT_MODE == 0) {
                    *reinterpret_cast<float2*>(Cf + z * sC + (size_t)row * ldC + col)
                        = make_float2(v0, v1);
                } else {
                    bf16 h0, h1, l0, l1;
                    split1(v0, h0, l0); split1(v1, h1, l1);
                    if (OUT_MODE == 1) {
                        const size_t idx = z * sC + (size_t)row * ldC + col;
                        *reinterpret_cast<uint32_t*>(Ch + idx) = packbf(h0, h1);
                        *reinterpret_cast<uint32_t*>(Cl + idx) = packbf(l0, l1);
                    } else {
                        Ch[z * sC + (size_t)col * ldC + row]       = h0;
                        Ch[z * sC + (size_t)(col + 1) * ldC + row] = h1;
                        Cl[z * sC + (size_t)col * ldC + row]       = l0;
                        Cl[z * sC + (size_t)(col + 1) * ldC + row] = l1;
                    }
                }
            }
        }
    }
}

// ---------------------------------------------------------------------------
// Row softmax (2048/row) -> bf16 hi/lo probability planes.
// ---------------------------------------------------------------------------
__global__ __launch_bounds__(256)
void softmax2048(const float* __restrict__ S, bf16* __restrict__ Ph,
                 bf16* __restrict__ Pl)
{
    const long long row = blockIdx.x;
    const float* p = S + row * 2048;
    const int tid = threadIdx.x;
    const int w = tid >> 5, l = tid & 31;

    float v[8];
    {
        float4 x0 = *reinterpret_cast<const float4*>(p + tid * 8);
        float4 x1 = *reinterpret_cast<const float4*>(p + tid * 8 + 4);
        v[0] = x0.x; v[1] = x0.y; v[2] = x0.z; v[3] = x0.w;
        v[4] = x1.x; v[5] = x1.y; v[6] = x1.z; v[7] = x1.w;
    }
    __shared__ float smax[8], ssum[8];

    float m = v[0];
#pragma unroll
    for (int j = 1; j < 8; j++) m = fmaxf(m, v[j]);
#pragma unroll
    for (int off = 16; off >= 1; off >>= 1)
        m = fmaxf(m, __shfl_xor_sync(0xffffffffu, m, off));
    if (l == 0) smax[w] = m;
    __syncthreads();
    float bm = smax[0];
#pragma unroll
    for (int j = 1; j < 8; j++) bm = fmaxf(bm, smax[j]);

    float s = 0.f;
#pragma unroll
    for (int j = 0; j < 8; j++) { v[j] = expf(v[j] - bm); s += v[j]; }
#pragma unroll
    for (int off = 16; off >= 1; off >>= 1)
        s += __shfl_xor_sync(0xffffffffu, s, off);
    if (l == 0) ssum[w] = s;
    __syncthreads();
    float tot = ssum[0];
#pragma unroll
    for (int j = 1; j < 8; j++) tot += ssum[j];

    const float inv = 1.f / tot;
    bf16 hh[8], ll[8];
#pragma unroll
    for (int j = 0; j < 8; j++) { v[j] *= inv; split1(v[j], hh[j], ll[j]); }

    const long long ob = row * 2048 + tid * 8;
    *reinterpret_cast<uint2*>(Ph + ob) =
        make_uint2(packbf(hh[0], hh[1]), packbf(hh[2], hh[3]));
    *reinterpret_cast<uint2*>(Ph + ob + 4) =
        make_uint2(packbf(hh[4], hh[5]), packbf(hh[6], hh[7]));
    *reinterpret_cast<uint2*>(Pl + ob) =
        make_uint2(packbf(ll[0], ll[1]), packbf(ll[2], ll[3]));
    *reinterpret_cast<uint2*>(Pl + ob + 4) =
        make_uint2(packbf(ll[4], ll[5]), packbf(ll[6], ll[7]));
}

// ---------------------------------------------------------------------------
extern "C" void kernel_launch(void* const* d_in, const int* in_sizes, int n_in,
                              void* d_out, int out_size)
{
    (void)in_sizes; (void)n_in; (void)out_size;
    const float* x  = (const float*)d_in[0];
    const float* ce = (const float*)d_in[1];
    const float* Wq = (const float*)d_in[2];
    const float* bq = (const float*)d_in[3];
    const float* Wk = (const float*)d_in[4];
    const float* bk = (const float*)d_in[5];
    const float* Wv = (const float*)d_in[6];
    const float* bv = (const float*)d_in[7];
    const float* Wo = (const float*)d_in[8];
    const float* bo = (const float*)d_in[9];
    float* out = (float*)d_out;

    float* S;
    bf16 *xh, *xl, *ceh, *cel, *Wqh, *Wql, *Wkh, *Wkl, *Wvh, *Wvl, *Woh, *Wol;
    bf16 *Qh, *Ql, *Kh, *Kl, *Vth, *Vtl, *Ph, *Pl, *Th, *Tl;
    cudaGetSymbolAddress((void**)&S,   g_S);
    cudaGetSymbolAddress((void**)&xh,  g_xh);  cudaGetSymbolAddress((void**)&xl,  g_xl);
    cudaGetSymbolAddress((void**)&ceh, g_ceh); cudaGetSymbolAddress((void**)&cel, g_cel);
    cudaGetSymbolAddress((void**)&Wqh, g_Wqh); cudaGetSymbolAddress((void**)&Wql, g_Wql);
    cudaGetSymbolAddress((void**)&Wkh, g_Wkh); cudaGetSymbolAddress((void**)&Wkl, g_Wkl);
    cudaGetSymbolAddress((void**)&Wvh, g_Wvh); cudaGetSymbolAddress((void**)&Wvl, g_Wvl);
    cudaGetSymbolAddress((void**)&Woh, g_Woh); cudaGetSymbolAddress((void**)&Wol, g_Wol);
    cudaGetSymbolAddress((void**)&Qh,  g_Qh);  cudaGetSymbolAddress((void**)&Ql,  g_Ql);
    cudaGetSymbolAddress((void**)&Kh,  g_Kh);  cudaGetSymbolAddress((void**)&Kl,  g_Kl);
    cudaGetSymbolAddress((void**)&Vth, g_Vth); cudaGetSymbolAddress((void**)&Vtl, g_Vtl);
    cudaGetSymbolAddress((void**)&Ph,  g_Ph);  cudaGetSymbolAddress((void**)&Pl,  g_Pl);
    cudaGetSymbolAddress((void**)&Th,  g_Th);  cudaGetSymbolAddress((void**)&Tl,  g_Tl);

    cudaFuncSetAttribute(gemm_bf<1, true,  false>, cudaFuncAttributeMaxDynamicSharedMemorySize, SMEM_TOTAL);
    cudaFuncSetAttribute(gemm_bf<2, true,  false>, cudaFuncAttributeMaxDynamicSharedMemorySize, SMEM_TOTAL);
    cudaFuncSetAttribute(gemm_bf<0, false, false>, cudaFuncAttributeMaxDynamicSharedMemorySize, SMEM_TOTAL);
    cudaFuncSetAttribute(gemm_bf<1, false, true >, cudaFuncAttributeMaxDynamicSharedMemorySize, SMEM_TOTAL);
    cudaFuncSetAttribute(gemm_bf<0, true,  false>, cudaFuncAttributeMaxDynamicSharedMemorySize, SMEM_TOTAL);

    split_kernel<<<M_ALL * C_DIM / 1024, 256>>>((const float4*)x,  (uint2*)xh,  (uint2*)xl);
    split_kernel<<<M_ALL * C_DIM / 1024, 256>>>((const float4*)ce, (uint2*)ceh, (uint2*)cel);
    split_kernel<<<C_DIM * C_DIM / 1024, 256>>>((const float4*)Wq, (uint2*)Wqh, (uint2*)Wql);
    split_kernel<<<C_DIM * C_DIM / 1024, 256>>>((const float4*)Wk, (uint2*)Wkh, (uint2*)Wkl);
    split_kernel<<<C_DIM * C_DIM / 1024, 256>>>((const float4*)Wv, (uint2*)Wvh, (uint2*)Wvl);
    split_kernel<<<C_DIM * C_DIM / 1024, 256>>>((const float4*)Wo, (uint2*)Woh, (uint2*)Wol);

    const long long sQ = (long long)S_DIM * C_DIM;
    const long long sS = (long long)S_DIM * S_DIM;

    // Q/K projections -> split bf16
    gemm_bf<1, true, false><<<dim3(8, 64, 1), 128, SMEM_TOTAL>>>(
        xh, xl, Wqh, Wql, bq, nullptr, nullptr, Qh, Ql,
        C_DIM, 1.f, C_DIM, C_DIM, C_DIM, 0, 0, 0, 0);
    gemm_bf<1, true, false><<<dim3(8, 64, 1), 128, SMEM_TOTAL>>>(
        ceh, cel, Wkh, Wkl, bk, nullptr, nullptr, Kh, Kl,
        C_DIM, 1.f, C_DIM, C_DIM, C_DIM, 0, 0, 0, 0);
    // V projection -> transposed split bf16 (Vt[ch][token])
    gemm_bf<2, true, false><<<dim3(8, 64, 1), 128, SMEM_TOTAL>>>(
        ceh, cel, Wvh, Wvl, bv, nullptr, nullptr, Vth, Vtl,
        C_DIM, 1.f, C_DIM, C_DIM, M_ALL, 0, 0, 0, 0);

    // scores: per-batch Q @ K^T / 32 -> fp32 S
    gemm_bf<0, false, false><<<dim3(16, 16, B_DIM), 128, SMEM_TOTAL>>>(
        Qh, Ql, Kh, Kl, nullptr, nullptr, S, nullptr, nullptr,
        C_DIM, 0.03125f, C_DIM, C_DIM, S_DIM, sQ, sQ, sS, 0);

    softmax2048<<<M_ALL, 256>>>(S, Ph, Pl);

    // attended + residual -> split bf16 T
    gemm_bf<1, false, true><<<dim3(8, 16, B_DIM), 128, SMEM_TOTAL>>>(
        Ph, Pl, Vth, Vtl, nullptr, x, nullptr, Th, Tl,
        S_DIM, 1.f, S_DIM, M_ALL, C_DIM, sS, S_DIM, sQ, sQ);

    // output projection -> fp32 out
    gemm_bf<0, true, false><<<dim3(8, 64, 1), 128, SMEM_TOTAL>>>(
        Th, Tl, Woh, Wol, bo, nullptr, out, nullptr, nullptr,
        C_DIM, 1.f, C_DIM, C_DIM, C_DIM, 0, 0, 0, 0);
}

// round 8
// speedup vs baseline: 1.2276x; 1.0577x over previous
#include <cuda_runtime.h>
#include <cuda_bf16.h>
#include <cstdint>
#include <math.h>

// ---------------------------------------------------------------------------
// SpatialTransformer via mma.sync bf16 (HMMA), hi/lo fp32 split.
// Round 8: fused QKV projection launch (wave packing), fused split pass.
// GEMM core identical to round 7 (64x64 warp tiles, 128 thr, 2 CTAs/SM).
// ---------------------------------------------------------------------------

#define B_DIM 4
#define S_DIM 2048
#define C_DIM 1024
#define M_ALL (B_DIM * S_DIM)   // 8192

typedef __nv_bfloat16 bf16;

__device__ float g_S[(long long)B_DIM * S_DIM * S_DIM];  // scores, 64 MB
__device__ bf16 g_xh[M_ALL * C_DIM],  g_xl[M_ALL * C_DIM];
__device__ bf16 g_ceh[M_ALL * C_DIM], g_cel[M_ALL * C_DIM];
__device__ bf16 g_Wqh[C_DIM * C_DIM], g_Wql[C_DIM * C_DIM];
__device__ bf16 g_Wkh[C_DIM * C_DIM], g_Wkl[C_DIM * C_DIM];
__device__ bf16 g_Wvh[C_DIM * C_DIM], g_Wvl[C_DIM * C_DIM];
__device__ bf16 g_Woh[C_DIM * C_DIM], g_Wol[C_DIM * C_DIM];
__device__ bf16 g_Qh[M_ALL * C_DIM],  g_Ql[M_ALL * C_DIM];
__device__ bf16 g_Kh[M_ALL * C_DIM],  g_Kl[M_ALL * C_DIM];
__device__ bf16 g_Vth[C_DIM * M_ALL], g_Vtl[C_DIM * M_ALL];
__device__ bf16 g_Ph[(long long)B_DIM * S_DIM * S_DIM], g_Pl[(long long)B_DIM * S_DIM * S_DIM];
__device__ bf16 g_Th[M_ALL * C_DIM],  g_Tl[M_ALL * C_DIM];

__device__ __forceinline__ uint32_t smem_u32(const void* p) {
    uint32_t a;
    asm("{ .reg .u64 t; cvta.to.shared.u64 t, %1; cvt.u32.u64 %0, t; }"
        : "=r"(a) : "l"(p));
    return a;
}

#define LDMX4(r0, r1, r2, r3, addr) \
    asm volatile("ldmatrix.sync.aligned.m8n8.x4.shared.b16 {%0,%1,%2,%3}, [%4];" \
                 : "=r"(r0), "=r"(r1), "=r"(r2), "=r"(r3) : "r"(addr))
#define MMA16816(d, a, b) \
    asm volatile("mma.sync.aligned.m16n8k16.row.col.f32.bf16.bf16.f32 " \
                 "{%0,%1,%2,%3}, {%4,%5,%6,%7}, {%8,%9}, {%0,%1,%2,%3};" \
                 : "+f"((d)[0]), "+f"((d)[1]), "+f"((d)[2]), "+f"((d)[3]) \
                 : "r"((a)[0]), "r"((a)[1]), "r"((a)[2]), "r"((a)[3]), \
                   "r"((b)[0]), "r"((b)[1]))
#define CP_ASYNC16(dst, src) \
    asm volatile("cp.async.cg.shared.global [%0], [%1], 16;" \
                 :: "r"(dst), "l"(src) : "memory")
#define CP_COMMIT() asm volatile("cp.async.commit_group;" ::: "memory")
#define CP_WAIT0()  asm volatile("cp.async.wait_group 0;" ::: "memory")
#define CP_WAIT1()  asm volatile("cp.async.wait_group 1;" ::: "memory")

#define KT        32
#define ROW_H     40
#define TILE_H    (128 * ROW_H)          // halves (5120)
#define STAGE_H   (4 * TILE_H)           // Ah, Al, Bh, Bl
#define SMEM_TOTAL (2 * STAGE_H * 2)     // bytes: 81920

__device__ __forceinline__ uint32_t packbf(bf16 a, bf16 b) {
    __nv_bfloat162 t; t.x = a; t.y = b;
    return *reinterpret_cast<uint32_t*>(&t);
}
__device__ __forceinline__ void split1(float v, bf16& h, bf16& l) {
    h = __float2bfloat16(v);
    l = __float2bfloat16(v - __bfloat162float(h));
}

// ---------------------------------------------------------------------------
// Fused pre-split of all six fp32 tensors -> planar bf16 hi/lo.
// Segments (in 256-thread blocks of 1024 floats): x 8192, ce 8192, W* 1024 each.
// ---------------------------------------------------------------------------
__global__ __launch_bounds__(256)
void split_all(const float4* __restrict__ x,  const float4* __restrict__ ce,
               const float4* __restrict__ Wq, const float4* __restrict__ Wk,
               const float4* __restrict__ Wv, const float4* __restrict__ Wo,
               uint2* __restrict__ xh,  uint2* __restrict__ xl,
               uint2* __restrict__ ceh, uint2* __restrict__ cel,
               uint2* __restrict__ Wqh, uint2* __restrict__ Wql,
               uint2* __restrict__ Wkh, uint2* __restrict__ Wkl,
               uint2* __restrict__ Wvh, uint2* __restrict__ Wvl,
               uint2* __restrict__ Woh, uint2* __restrict__ Wol)
{
    const int b = blockIdx.x;
    const float4* in; uint2* oh; uint2* ol; int lb;
    if (b < 8192)       { in = x;  oh = xh;  ol = xl;  lb = b; }
    else if (b < 16384) { in = ce; oh = ceh; ol = cel; lb = b - 8192; }
    else if (b < 17408) { in = Wq; oh = Wqh; ol = Wql; lb = b - 16384; }
    else if (b < 18432) { in = Wk; oh = Wkh; ol = Wkl; lb = b - 17408; }
    else if (b < 19456) { in = Wv; oh = Wvh; ol = Wvl; lb = b - 18432; }
    else                { in = Wo; oh = Woh; ol = Wol; lb = b - 19456; }

    const int i = lb * 256 + threadIdx.x;
    float4 v = in[i];
    bf16 h0, h1, h2, h3, l0, l1, l2, l3;
    split1(v.x, h0, l0); split1(v.y, h1, l1);
    split1(v.z, h2, l2); split1(v.w, h3, l3);
    oh[i] = make_uint2(packbf(h0, h1), packbf(h2, h3));
    ol[i] = make_uint2(packbf(l0, l1), packbf(l2, l3));
}

// ---------------------------------------------------------------------------
// Shared GEMM mainloop: acc += A@B^T over K, operands planar bf16 hi/lo.
// 128x128 block tile, 128 threads, 4 warps of 64x64, 2-stage cp.async.
// ---------------------------------------------------------------------------
__device__ __forceinline__ void gemm_core(
    const bf16* __restrict__ Agh, const bf16* __restrict__ Agl,
    const bf16* __restrict__ Bgh, const bf16* __restrict__ Bgl,
    int ldA, int ldB, int K, char* smem_raw, float acc[4][8][4])
{
    const uint32_t sm_base = smem_u32(smem_raw);
    const int tid  = threadIdx.x;
    const int lane = tid & 31;
    const int wid  = tid >> 5;

    const int warp_m = (wid & 1) * 64;
    const int warp_n = (wid >> 1) * 64;

    const int r0 = tid >> 2;
    const int kc = (tid & 3) * 8;

    const int arow  = warp_m + (lane & 15);
    const int acolr = (lane >> 4) << 3;
    const int brow_off = ((lane >> 4) << 3) + (lane & 7);
    const int bcolr = lane & 8;

    const int NK = K >> 5;

    auto load_stage = [&](int buf, int kt) {
        const uint32_t sbase = sm_base + (uint32_t)(buf * STAGE_H) * 2;
        const int kk = kt * KT + kc;
#pragma unroll
        for (int rr = 0; rr < 4; rr++) {
            const int row = r0 + rr * 32;
            const uint32_t so = (uint32_t)(row * ROW_H + kc) * 2;
            CP_ASYNC16(sbase + so,                              Agh + (size_t)row * ldA + kk);
            CP_ASYNC16(sbase + (uint32_t)(TILE_H * 2) + so,     Agl + (size_t)row * ldA + kk);
            CP_ASYNC16(sbase + (uint32_t)(2 * TILE_H * 2) + so, Bgh + (size_t)row * ldB + kk);
            CP_ASYNC16(sbase + (uint32_t)(3 * TILE_H * 2) + so, Bgl + (size_t)row * ldB + kk);
        }
    };

    load_stage(0, 0);
    CP_COMMIT();

    for (int kt = 0; kt < NK; ++kt) {
        const int buf = kt & 1;
        if (kt + 1 < NK) {
            load_stage(buf ^ 1, kt + 1);
            CP_COMMIT();
            CP_WAIT1();
        } else {
            CP_WAIT0();
        }
        __syncthreads();

        const uint32_t stg = sm_base + (uint32_t)(buf * STAGE_H) * 2;
#pragma unroll
        for (int half = 0; half < 2; ++half) {
            const int kk = half * 16;
            uint32_t af[4][4];
            uint32_t bh[8][2], bl[8][2];

#pragma unroll
            for (int i = 0; i < 4; i++) {
                const uint32_t byt = (uint32_t)(((arow + i * 16) * ROW_H + kk + acolr) * 2);
                LDMX4(af[i][0], af[i][1], af[i][2], af[i][3], stg + byt);
            }
#pragma unroll
            for (int jj = 0; jj < 8; jj += 2) {
                const uint32_t byt =
                    (uint32_t)(((warp_n + jj * 8 + brow_off) * ROW_H + kk + bcolr) * 2);
                LDMX4(bh[jj][0], bh[jj][1], bh[jj + 1][0], bh[jj + 1][1],
                      stg + (uint32_t)(2 * TILE_H * 2) + byt);
            }
#pragma unroll
            for (int i = 0; i < 4; i++)
#pragma unroll
                for (int j = 0; j < 8; j++)
                    MMA16816(acc[i][j], af[i], bh[j]);

#pragma unroll
            for (int jj = 0; jj < 8; jj += 2) {
                const uint32_t byt =
                    (uint32_t)(((warp_n + jj * 8 + brow_off) * ROW_H + kk + bcolr) * 2);
                LDMX4(bl[jj][0], bl[jj][1], bl[jj + 1][0], bl[jj + 1][1],
                      stg + (uint32_t)(3 * TILE_H * 2) + byt);
            }
#pragma unroll
            for (int i = 0; i < 4; i++)
#pragma unroll
                for (int j = 0; j < 8; j++)
                    MMA16816(acc[i][j], af[i], bl[j]);

#pragma unroll
            for (int i = 0; i < 4; i++) {
                const uint32_t byt = (uint32_t)(((arow + i * 16) * ROW_H + kk + acolr) * 2);
                LDMX4(af[i][0], af[i][1], af[i][2], af[i][3],
                      stg + (uint32_t)(TILE_H * 2) + byt);
            }
#pragma unroll
            for (int i = 0; i < 4; i++)
#pragma unroll
                for (int j = 0; j < 8; j++)
                    MMA16816(acc[i][j], af[i], bh[j]);
        }
        __syncthreads();
    }
}

// ---------------------------------------------------------------------------
// Fused Q/K/V projection: grid (8, 64, 3); z=0 Q, z=1 K, z=2 V(transposed).
// ---------------------------------------------------------------------------
__global__ __launch_bounds__(128, 2)
void gemm_qkv(const bf16* __restrict__ xh,  const bf16* __restrict__ xl,
              const bf16* __restrict__ ceh, const bf16* __restrict__ cel,
              const bf16* __restrict__ Wqh, const bf16* __restrict__ Wql,
              const bf16* __restrict__ Wkh, const bf16* __restrict__ Wkl,
              const bf16* __restrict__ Wvh, const bf16* __restrict__ Wvl,
              const float* __restrict__ bq, const float* __restrict__ bk,
              const float* __restrict__ bv,
              bf16* __restrict__ Qh,  bf16* __restrict__ Ql,
              bf16* __restrict__ Kh,  bf16* __restrict__ Kl,
              bf16* __restrict__ Vth, bf16* __restrict__ Vtl)
{
    extern __shared__ __align__(16) char smem_raw[];
    const int z  = blockIdx.z;
    const int m0 = blockIdx.y * 128;
    const int n0 = blockIdx.x * 128;

    const bf16 *Ah_, *Al_, *Bh_, *Bl_;
    const float* bias;
    if (z == 0)      { Ah_ = xh;  Al_ = xl;  Bh_ = Wqh; Bl_ = Wql; bias = bq; }
    else if (z == 1) { Ah_ = ceh; Al_ = cel; Bh_ = Wkh; Bl_ = Wkl; bias = bk; }
    else             { Ah_ = ceh; Al_ = cel; Bh_ = Wvh; Bl_ = Wvl; bias = bv; }

    float acc[4][8][4];
#pragma unroll
    for (int i = 0; i < 4; i++)
#pragma unroll
        for (int j = 0; j < 8; j++)
#pragma unroll
            for (int c = 0; c < 4; c++) acc[i][j][c] = 0.f;

    gemm_core(Ah_ + (size_t)m0 * C_DIM, Al_ + (size_t)m0 * C_DIM,
              Bh_ + (size_t)n0 * C_DIM, Bl_ + (size_t)n0 * C_DIM,
              C_DIM, C_DIM, C_DIM, smem_raw, acc);

    const int tid  = threadIdx.x;
    const int wid  = tid >> 5;
    const int lane = tid & 31;
    const int warp_m = (wid & 1) * 64;
    const int warp_n = (wid >> 1) * 64;
    const int gq = lane >> 2;
    const int tq = lane & 3;

#pragma unroll
    for (int i = 0; i < 4; i++) {
#pragma unroll
        for (int j = 0; j < 8; j++) {
            const int col = n0 + warp_n + j * 8 + tq * 2;
#pragma unroll
            for (int h = 0; h < 2; h++) {
                const int row = m0 + warp_m + i * 16 + gq + h * 8;
                float2 bb = *reinterpret_cast<const float2*>(bias + col);
                float v0 = acc[i][j][2 * h]     + bb.x;
                float v1 = acc[i][j][2 * h + 1] + bb.y;
                bf16 h0, h1, l0, l1;
                split1(v0, h0, l0); split1(v1, h1, l1);
                if (z == 0) {
                    const size_t idx = (size_t)row * C_DIM + col;
                    *reinterpret_cast<uint32_t*>(Qh + idx) = packbf(h0, h1);
                    *reinterpret_cast<uint32_t*>(Ql + idx) = packbf(l0, l1);
                } else if (z == 1) {
                    const size_t idx = (size_t)row * C_DIM + col;
                    *reinterpret_cast<uint32_t*>(Kh + idx) = packbf(h0, h1);
                    *reinterpret_cast<uint32_t*>(Kl + idx) = packbf(l0, l1);
                } else {
                    Vth[(size_t)col * M_ALL + row]       = h0;
                    Vth[(size_t)(col + 1) * M_ALL + row] = h1;
                    Vtl[(size_t)col * M_ALL + row]       = l0;
                    Vtl[(size_t)(col + 1) * M_ALL + row] = l1;
                }
            }
        }
    }
}

// ---------------------------------------------------------------------------
// Generic GEMM kernels (scores / attnV / outproj), same core.
// OUT_MODE: 0 = fp32 out, 1 = split bf16 hi/lo out.
// ---------------------------------------------------------------------------
template<int OUT_MODE, bool HAS_BIAS, bool HAS_RES>
__global__ __launch_bounds__(128, 2)
void gemm_bf(const bf16* __restrict__ Ah, const bf16* __restrict__ Al,
             const bf16* __restrict__ Bh, const bf16* __restrict__ Bl,
             const float* __restrict__ bias, const float* __restrict__ Rm,
             float* __restrict__ Cf, bf16* __restrict__ Ch, bf16* __restrict__ Cl,
             int K, float alpha, int ldA, int ldB, int ldC,
             long long sA, long long sB, long long sC, long long sR)
{
    extern __shared__ __align__(16) char smem_raw[];
    const int z  = blockIdx.z;
    const int m0 = blockIdx.y * 128;
    const int n0 = blockIdx.x * 128;

    float acc[4][8][4];
#pragma unroll
    for (int i = 0; i < 4; i++)
#pragma unroll
        for (int j = 0; j < 8; j++)
#pragma unroll
            for (int c = 0; c < 4; c++) acc[i][j][c] = 0.f;

    gemm_core(Ah + z * sA + (size_t)m0 * ldA, Al + z * sA + (size_t)m0 * ldA,
              Bh + z * sB + (size_t)n0 * ldB, Bl + z * sB + (size_t)n0 * ldB,
              ldA, ldB, K, smem_raw, acc);

    const int tid  = threadIdx.x;
    const int wid  = tid >> 5;
    const int lane = tid & 31;
    const int warp_m = (wid & 1) * 64;
    const int warp_n = (wid >> 1) * 64;
    const int gq = lane >> 2;
    const int tq = lane & 3;

#pragma unroll
    for (int i = 0; i < 4; i++) {
#pragma unroll
        for (int j = 0; j < 8; j++) {
            const int col = n0 + warp_n + j * 8 + tq * 2;
#pragma unroll
            for (int h = 0; h < 2; h++) {
                const int row = m0 + warp_m + i * 16 + gq + h * 8;
                float v0 = acc[i][j][2 * h]     * alpha;
                float v1 = acc[i][j][2 * h + 1] * alpha;
                if (HAS_BIAS) {
                    float2 bb = *reinterpret_cast<const float2*>(bias + col);
                    v0 += bb.x; v1 += bb.y;
                }
                if (HAS_RES) {
                    float2 r = *reinterpret_cast<const float2*>(
                        Rm + z * sR + (size_t)row * ldC + col);
                    v0 += r.x; v1 += r.y;
                }
                if (OUT_MODE == 0) {
                    *reinterpret_cast<float2*>(Cf + z * sC + (size_t)row * ldC + col)
                        = make_float2(v0, v1);
                } else {
                    bf16 h0, h1, l0, l1;
                    split1(v0, h0, l0); split1(v1, h1, l1);
                    const size_t idx = z * sC + (size_t)row * ldC + col;
                    *reinterpret_cast<uint32_t*>(Ch + idx) = packbf(h0, h1);
                    *reinterpret_cast<uint32_t*>(Cl + idx) = packbf(l0, l1);
                }
            }
        }
    }
}

// ---------------------------------------------------------------------------
// Row softmax (2048/row) -> bf16 hi/lo probability planes.
// ---------------------------------------------------------------------------
__global__ __launch_bounds__(256)
void softmax2048(const float* __restrict__ S, bf16* __restrict__ Ph,
                 bf16* __restrict__ Pl)
{
    const long long row = blockIdx.x;
    const float* p = S + row * 2048;
    const int tid = threadIdx.x;
    const int w = tid >> 5, l = tid & 31;

    float v[8];
    {
        float4 x0 = *reinterpret_cast<const float4*>(p + tid * 8);
        float4 x1 = *reinterpret_cast<const float4*>(p + tid * 8 + 4);
        v[0] = x0.x; v[1] = x0.y; v[2] = x0.z; v[3] = x0.w;
        v[4] = x1.x; v[5] = x1.y; v[6] = x1.z; v[7] = x1.w;
    }
    __shared__ float smax[8], ssum[8];

    float m = v[0];
#pragma unroll
    for (int j = 1; j < 8; j++) m = fmaxf(m, v[j]);
#pragma unroll
    for (int off = 16; off >= 1; off >>= 1)
        m = fmaxf(m, __shfl_xor_sync(0xffffffffu, m, off));
    if (l == 0) smax[w] = m;
    __syncthreads();
    float bm = smax[0];
#pragma unroll
    for (int j = 1; j < 8; j++) bm = fmaxf(bm, smax[j]);

    float s = 0.f;
#pragma unroll
    for (int j = 0; j < 8; j++) { v[j] = expf(v[j] - bm); s += v[j]; }
#pragma unroll
    for (int off = 16; off >= 1; off >>= 1)
        s += __shfl_xor_sync(0xffffffffu, s, off);
    if (l == 0) ssum[w] = s;
    __syncthreads();
    float tot = ssum[0];
#pragma unroll
    for (int j = 1; j < 8; j++) tot += ssum[j];

    const float inv = 1.f / tot;
    bf16 hh[8], ll[8];
#pragma unroll
    for (int j = 0; j < 8; j++) { v[j] *= inv; split1(v[j], hh[j], ll[j]); }

    const long long ob = row * 2048 + tid * 8;
    *reinterpret_cast<uint2*>(Ph + ob) =
        make_uint2(packbf(hh[0], hh[1]), packbf(hh[2], hh[3]));
    *reinterpret_cast<uint2*>(Ph + ob + 4) =
        make_uint2(packbf(hh[4], hh[5]), packbf(hh[6], hh[7]));
    *reinterpret_cast<uint2*>(Pl + ob) =
        make_uint2(packbf(ll[0], ll[1]), packbf(ll[2], ll[3]));
    *reinterpret_cast<uint2*>(Pl + ob + 4) =
        make_uint2(packbf(ll[4], ll[5]), packbf(ll[6], ll[7]));
}

// ---------------------------------------------------------------------------
extern "C" void kernel_launch(void* const* d_in, const int* in_sizes, int n_in,
                              void* d_out, int out_size)
{
    (void)in_sizes; (void)n_in; (void)out_size;
    const float* x  = (const float*)d_in[0];
    const float* ce = (const float*)d_in[1];
    const float* Wq = (const float*)d_in[2];
    const float* bq = (const float*)d_in[3];
    const float* Wk = (const float*)d_in[4];
    const float* bk = (const float*)d_in[5];
    const float* Wv = (const float*)d_in[6];
    const float* bv = (const float*)d_in[7];
    const float* Wo = (const float*)d_in[8];
    const float* bo = (const float*)d_in[9];
    float* out = (float*)d_out;

    float* S;
    bf16 *xh, *xl, *ceh, *cel, *Wqh, *Wql, *Wkh, *Wkl, *Wvh, *Wvl, *Woh, *Wol;
    bf16 *Qh, *Ql, *Kh, *Kl, *Vth, *Vtl, *Ph, *Pl, *Th, *Tl;
    cudaGetSymbolAddress((void**)&S,   g_S);
    cudaGetSymbolAddress((void**)&xh,  g_xh);  cudaGetSymbolAddress((void**)&xl,  g_xl);
    cudaGetSymbolAddress((void**)&ceh, g_ceh); cudaGetSymbolAddress((void**)&cel, g_cel);
    cudaGetSymbolAddress((void**)&Wqh, g_Wqh); cudaGetSymbolAddress((void**)&Wql, g_Wql);
    cudaGetSymbolAddress((void**)&Wkh, g_Wkh); cudaGetSymbolAddress((void**)&Wkl, g_Wkl);
    cudaGetSymbolAddress((void**)&Wvh, g_Wvh); cudaGetSymbolAddress((void**)&Wvl, g_Wvl);
    cudaGetSymbolAddress((void**)&Woh, g_Woh); cudaGetSymbolAddress((void**)&Wol, g_Wol);
    cudaGetSymbolAddress((void**)&Qh,  g_Qh);  cudaGetSymbolAddress((void**)&Ql,  g_Ql);
    cudaGetSymbolAddress((void**)&Kh,  g_Kh);  cudaGetSymbolAddress((void**)&Kl,  g_Kl);
    cudaGetSymbolAddress((void**)&Vth, g_Vth); cudaGetSymbolAddress((void**)&Vtl, g_Vtl);
    cudaGetSymbolAddress((void**)&Ph,  g_Ph);  cudaGetSymbolAddress((void**)&Pl,  g_Pl);
    cudaGetSymbolAddress((void**)&Th,  g_Th);  cudaGetSymbolAddress((void**)&Tl,  g_Tl);

    cudaFuncSetAttribute(gemm_qkv, cudaFuncAttributeMaxDynamicSharedMemorySize, SMEM_TOTAL);
    cudaFuncSetAttribute(gemm_bf<0, false, false>, cudaFuncAttributeMaxDynamicSharedMemorySize, SMEM_TOTAL);
    cudaFuncSetAttribute(gemm_bf<1, false, true >, cudaFuncAttributeMaxDynamicSharedMemorySize, SMEM_TOTAL);
    cudaFuncSetAttribute(gemm_bf<0, true,  false>, cudaFuncAttributeMaxDynamicSharedMemorySize, SMEM_TOTAL);

    // fused pre-split of all inputs (20480 blocks)
    split_all<<<20480, 256>>>(
        (const float4*)x, (const float4*)ce, (const float4*)Wq,
        (const float4*)Wk, (const float4*)Wv, (const float4*)Wo,
        (uint2*)xh, (uint2*)xl, (uint2*)ceh, (uint2*)cel,
        (uint2*)Wqh, (uint2*)Wql, (uint2*)Wkh, (uint2*)Wkl,
        (uint2*)Wvh, (uint2*)Wvl, (uint2*)Woh, (uint2*)Wol);

    const long long sQ = (long long)S_DIM * C_DIM;
    const long long sS = (long long)S_DIM * S_DIM;

    // fused Q/K/V projections (one launch, 1536 CTAs)
    gemm_qkv<<<dim3(8, 64, 3), 128, SMEM_TOTAL>>>(
        xh, xl, ceh, cel, Wqh, Wql, Wkh, Wkl, Wvh, Wvl,
        bq, bk, bv, Qh, Ql, Kh, Kl, Vth, Vtl);

    // scores: per-batch Q @ K^T / 32 -> fp32 S
    gemm_bf<0, false, false><<<dim3(16, 16, B_DIM), 128, SMEM_TOTAL>>>(
        Qh, Ql, Kh, Kl, nullptr, nullptr, S, nullptr, nullptr,
        C_DIM, 0.03125f, C_DIM, C_DIM, S_DIM, sQ, sQ, sS, 0);

    softmax2048<<<M_ALL, 256>>>(S, Ph, Pl);

    // attended + residual -> split bf16 T
    gemm_bf<1, false, true><<<dim3(8, 16, B_DIM), 128, SMEM_TOTAL>>>(
        Ph, Pl, Vth, Vtl, nullptr, x, nullptr, Th, Tl,
        S_DIM, 1.f, S_DIM, M_ALL, C_DIM, sS, S_DIM, sQ, sQ);

    // output projection -> fp32 out
    gemm_bf<0, true, false><<<dim3(8, 64, 1), 128, SMEM_TOTAL>>>(
        Th, Tl, Woh, Wol, bo, nullptr, out, nullptr, nullptr,
        C_DIM, 1.f, C_DIM, C_DIM, C_DIM, 0, 0, 0, 0);
}

// round 9
// speedup vs baseline: 1.5749x; 1.2829x over previous
#include <cuda_runtime.h>
#include <cuda_fp16.h>
#include <cstdint>
#include <math.h>

// ---------------------------------------------------------------------------
// SpatialTransformer via mma.sync fp16 (HMMA), hi/lo fp32 split.
// Round 9: fp16 2-pass (split A, round B) for qkv/scores/attnV; 3-pass for
// out-projection. 3-stage cp.async ring. 64x64 warp tiles, 2 CTAs/SM.
// ---------------------------------------------------------------------------

#define B_DIM 4
#define S_DIM 2048
#define C_DIM 1024
#define M_ALL (B_DIM * S_DIM)   // 8192

__device__ float g_S[(long long)B_DIM * S_DIM * S_DIM];  // scores, 64 MB
// fp16 planes
__device__ half g_xh[M_ALL * C_DIM],  g_xl[M_ALL * C_DIM];
__device__ half g_ceh[M_ALL * C_DIM], g_cel[M_ALL * C_DIM];
__device__ half g_Wq[C_DIM * C_DIM];          // rounded once (B side)
__device__ half g_Wk[C_DIM * C_DIM];
__device__ half g_Wv[C_DIM * C_DIM];
__device__ half g_Woh[C_DIM * C_DIM], g_Wol[C_DIM * C_DIM];  // split (3-pass)
__device__ half g_Qh[M_ALL * C_DIM],  g_Ql[M_ALL * C_DIM];
__device__ half g_K[M_ALL * C_DIM];           // rounded once
__device__ half g_Vt[C_DIM * M_ALL];          // rounded once, transposed
__device__ half g_Ph[(long long)B_DIM * S_DIM * S_DIM];
__device__ half g_Pl[(long long)B_DIM * S_DIM * S_DIM];
__device__ half g_Th[M_ALL * C_DIM],  g_Tl[M_ALL * C_DIM];

__device__ __forceinline__ uint32_t smem_u32(const void* p) {
    uint32_t a;
    asm("{ .reg .u64 t; cvta.to.shared.u64 t, %1; cvt.u32.u64 %0, t; }"
        : "=r"(a) : "l"(p));
    return a;
}

#define LDMX4(r0, r1, r2, r3, addr) \
    asm volatile("ldmatrix.sync.aligned.m8n8.x4.shared.b16 {%0,%1,%2,%3}, [%4];" \
                 : "=r"(r0), "=r"(r1), "=r"(r2), "=r"(r3) : "r"(addr))
#define MMA16816(d, a, b) \
    asm volatile("mma.sync.aligned.m16n8k16.row.col.f32.f16.f16.f32 " \
                 "{%0,%1,%2,%3}, {%4,%5,%6,%7}, {%8,%9}, {%0,%1,%2,%3};" \
                 : "+f"((d)[0]), "+f"((d)[1]), "+f"((d)[2]), "+f"((d)[3]) \
                 : "r"((a)[0]), "r"((a)[1]), "r"((a)[2]), "r"((a)[3]), \
                   "r"((b)[0]), "r"((b)[1]))
#define CP_ASYNC16(dst, src) \
    asm volatile("cp.async.cg.shared.global [%0], [%1], 16;" \
                 :: "r"(dst), "l"(src) : "memory")
#define CP_COMMIT() asm volatile("cp.async.commit_group;" ::: "memory")

#define KT        32
#define ROW_H     40
#define TILE_H    (128 * ROW_H)          // halves (5120)
// 2-pass core: 3 tiles/stage (Ah, Al, B), 3 stages
#define STAGE2_H  (3 * TILE_H)
#define SMEM2     (3 * STAGE2_H * 2)     // 92160 B
// 3-pass core: 4 tiles/stage (Ah, Al, Bh, Bl), 2 stages
#define STAGE3_H  (4 * TILE_H)
#define SMEM3     (2 * STAGE3_H * 2)     // 81920 B

__device__ __forceinline__ uint32_t packh(half a, half b) {
    __half2 t; t.x = a; t.y = b;
    return *reinterpret_cast<uint32_t*>(&t);
}
__device__ __forceinline__ void split1h(float v, half& h, half& l) {
    h = __float2half(v);
    l = __float2half(v - __half2float(h));
}

// ---------------------------------------------------------------------------
// Fused pre-split: x, ce -> hi/lo; Wq/Wk/Wv -> rounded; Wo -> hi/lo.
// Block segments of 1024 floats: x 8192, ce 8192, each W 1024.
// ---------------------------------------------------------------------------
__global__ __launch_bounds__(256)
void split_all(const float4* __restrict__ x,  const float4* __restrict__ ce,
               const float4* __restrict__ Wq, const float4* __restrict__ Wk,
               const float4* __restrict__ Wv, const float4* __restrict__ Wo,
               uint2* __restrict__ xh,  uint2* __restrict__ xl,
               uint2* __restrict__ ceh, uint2* __restrict__ cel,
               uint2* __restrict__ Wq1, uint2* __restrict__ Wk1,
               uint2* __restrict__ Wv1,
               uint2* __restrict__ Woh, uint2* __restrict__ Wol)
{
    const int b = blockIdx.x;
    const float4* in; uint2* oh; uint2* ol; int lb;
    if (b < 8192)       { in = x;  oh = xh;  ol = xl;   lb = b; }
    else if (b < 16384) { in = ce; oh = ceh; ol = cel;  lb = b - 8192; }
    else if (b < 17408) { in = Wq; oh = Wq1; ol = 0;    lb = b - 16384; }
    else if (b < 18432) { in = Wk; oh = Wk1; ol = 0;    lb = b - 17408; }
    else if (b < 19456) { in = Wv; oh = Wv1; ol = 0;    lb = b - 18432; }
    else                { in = Wo; oh = Woh; ol = Wol;  lb = b - 19456; }

    const int i = lb * 256 + threadIdx.x;
    float4 v = in[i];
    half h0, h1, h2, h3, l0, l1, l2, l3;
    split1h(v.x, h0, l0); split1h(v.y, h1, l1);
    split1h(v.z, h2, l2); split1h(v.w, h3, l3);
    oh[i] = make_uint2(packh(h0, h1), packh(h2, h3));
    if (ol) ol[i] = make_uint2(packh(l0, l1), packh(l2, l3));
}

// ---------------------------------------------------------------------------
// 2-pass mainloop: acc += (Ah+Al)@B^T. 3 smem tiles/stage, 3-stage ring.
// ---------------------------------------------------------------------------
__device__ __forceinline__ void gemm_core2(
    const half* __restrict__ Agh, const half* __restrict__ Agl,
    const half* __restrict__ Bg,
    int ldA, int ldB, int K, char* smem_raw, float acc[4][8][4])
{
    const uint32_t sm_base = smem_u32(smem_raw);
    const int tid  = threadIdx.x;
    const int lane = tid & 31;
    const int wid  = tid >> 5;

    const int warp_m = (wid & 1) * 64;
    const int warp_n = (wid >> 1) * 64;

    const int r0 = tid >> 2;
    const int kc = (tid & 3) * 8;

    const int arow  = warp_m + (lane & 15);
    const int acolr = (lane >> 4) << 3;
    const int brow_off = ((lane >> 4) << 3) + (lane & 7);
    const int bcolr = lane & 8;

    const int NK = K >> 5;

    auto load_stage = [&](int buf, int kt) {
        const uint32_t sbase = sm_base + (uint32_t)(buf * STAGE2_H) * 2;
        const int kk = kt * KT + kc;
#pragma unroll
        for (int rr = 0; rr < 4; rr++) {
            const int row = r0 + rr * 32;
            const uint32_t so = (uint32_t)(row * ROW_H + kc) * 2;
            CP_ASYNC16(sbase + so,                              Agh + (size_t)row * ldA + kk);
            CP_ASYNC16(sbase + (uint32_t)(TILE_H * 2) + so,     Agl + (size_t)row * ldA + kk);
            CP_ASYNC16(sbase + (uint32_t)(2 * TILE_H * 2) + so, Bg  + (size_t)row * ldB + kk);
        }
    };

    load_stage(0, 0);
    CP_COMMIT();
    load_stage(1, 1);
    CP_COMMIT();

    for (int kt = 0; kt < NK; ++kt) {
        if (kt + 2 < NK) {
            load_stage((kt + 2) % 3, kt + 2);
            CP_COMMIT();
        }
        const int rem = NK - 1 - kt;   // groups committed after kt's
        if (rem >= 2)      asm volatile("cp.async.wait_group 2;" ::: "memory");
        else if (rem == 1) asm volatile("cp.async.wait_group 1;" ::: "memory");
        else               asm volatile("cp.async.wait_group 0;" ::: "memory");
        __syncthreads();

        const uint32_t stg = sm_base + (uint32_t)((kt % 3) * STAGE2_H) * 2;
#pragma unroll
        for (int half_ = 0; half_ < 2; ++half_) {
            const int kk = half_ * 16;
            uint32_t af[4][4];          // reused: hi then lo
            uint32_t bb[8][2];

#pragma unroll
            for (int i = 0; i < 4; i++) {
                const uint32_t byt = (uint32_t)(((arow + i * 16) * ROW_H + kk + acolr) * 2);
                LDMX4(af[i][0], af[i][1], af[i][2], af[i][3], stg + byt);
            }
#pragma unroll
            for (int jj = 0; jj < 8; jj += 2) {
                const uint32_t byt =
                    (uint32_t)(((warp_n + jj * 8 + brow_off) * ROW_H + kk + bcolr) * 2);
                LDMX4(bb[jj][0], bb[jj][1], bb[jj + 1][0], bb[jj + 1][1],
                      stg + (uint32_t)(2 * TILE_H * 2) + byt);
            }
            // pass 1: Ah*B
#pragma unroll
            for (int i = 0; i < 4; i++)
#pragma unroll
                for (int j = 0; j < 8; j++)
                    MMA16816(acc[i][j], af[i], bb[j]);
            // A lo into same regs
#pragma unroll
            for (int i = 0; i < 4; i++) {
                const uint32_t byt = (uint32_t)(((arow + i * 16) * ROW_H + kk + acolr) * 2);
                LDMX4(af[i][0], af[i][1], af[i][2], af[i][3],
                      stg + (uint32_t)(TILE_H * 2) + byt);
            }
            // pass 2: Al*B
#pragma unroll
            for (int i = 0; i < 4; i++)
#pragma unroll
                for (int j = 0; j < 8; j++)
                    MMA16816(acc[i][j], af[i], bb[j]);
        }
        __syncthreads();
    }
}

// ---------------------------------------------------------------------------
// 3-pass mainloop (outproj): acc += Ah*Bh + Ah*Bl + Al*Bh. 2-stage.
// ---------------------------------------------------------------------------
__device__ __forceinline__ void gemm_core3(
    const half* __restrict__ Agh, const half* __restrict__ Agl,
    const half* __restrict__ Bgh, const half* __restrict__ Bgl,
    int ldA, int ldB, int K, char* smem_raw, float acc[4][8][4])
{
    const uint32_t sm_base = smem_u32(smem_raw);
    const int tid  = threadIdx.x;
    const int lane = tid & 31;
    const int wid  = tid >> 5;

    const int warp_m = (wid & 1) * 64;
    const int warp_n = (wid >> 1) * 64;

    const int r0 = tid >> 2;
    const int kc = (tid & 3) * 8;

    const int arow  = warp_m + (lane & 15);
    const int acolr = (lane >> 4) << 3;
    const int brow_off = ((lane >> 4) << 3) + (lane & 7);
    const int bcolr = lane & 8;

    const int NK = K >> 5;

    auto load_stage = [&](int buf, int kt) {
        const uint32_t sbase = sm_base + (uint32_t)(buf * STAGE3_H) * 2;
        const int kk = kt * KT + kc;
#pragma unroll
        for (int rr = 0; rr < 4; rr++) {
            const int row = r0 + rr * 32;
            const uint32_t so = (uint32_t)(row * ROW_H + kc) * 2;
            CP_ASYNC16(sbase + so,                              Agh + (size_t)row * ldA + kk);
            CP_ASYNC16(sbase + (uint32_t)(TILE_H * 2) + so,     Agl + (size_t)row * ldA + kk);
            CP_ASYNC16(sbase + (uint32_t)(2 * TILE_H * 2) + so, Bgh + (size_t)row * ldB + kk);
            CP_ASYNC16(sbase + (uint32_t)(3 * TILE_H * 2) + so, Bgl + (size_t)row * ldB + kk);
        }
    };

    load_stage(0, 0);
    CP_COMMIT();

    for (int kt = 0; kt < NK; ++kt) {
        const int buf = kt & 1;
        if (kt + 1 < NK) {
            load_stage(buf ^ 1, kt + 1);
            CP_COMMIT();
            asm volatile("cp.async.wait_group 1;" ::: "memory");
        } else {
            asm volatile("cp.async.wait_group 0;" ::: "memory");
        }
        __syncthreads();

        const uint32_t stg = sm_base + (uint32_t)(buf * STAGE3_H) * 2;
#pragma unroll
        for (int half_ = 0; half_ < 2; ++half_) {
            const int kk = half_ * 16;
            uint32_t af[4][4];
            uint32_t bh[8][2], bl[8][2];

#pragma unroll
            for (int i = 0; i < 4; i++) {
                const uint32_t byt = (uint32_t)(((arow + i * 16) * ROW_H + kk + acolr) * 2);
                LDMX4(af[i][0], af[i][1], af[i][2], af[i][3], stg + byt);
            }
#pragma unroll
            for (int jj = 0; jj < 8; jj += 2) {
                const uint32_t byt =
                    (uint32_t)(((warp_n + jj * 8 + brow_off) * ROW_H + kk + bcolr) * 2);
                LDMX4(bh[jj][0], bh[jj][1], bh[jj + 1][0], bh[jj + 1][1],
                      stg + (uint32_t)(2 * TILE_H * 2) + byt);
            }
#pragma unroll
            for (int i = 0; i < 4; i++)
#pragma unroll
                for (int j = 0; j < 8; j++)
                    MMA16816(acc[i][j], af[i], bh[j]);

#pragma unroll
            for (int jj = 0; jj < 8; jj += 2) {
                const uint32_t byt =
                    (uint32_t)(((warp_n + jj * 8 + brow_off) * ROW_H + kk + bcolr) * 2);
                LDMX4(bl[jj][0], bl[jj][1], bl[jj + 1][0], bl[jj + 1][1],
                      stg + (uint32_t)(3 * TILE_H * 2) + byt);
            }
#pragma unroll
            for (int i = 0; i < 4; i++)
#pragma unroll
                for (int j = 0; j < 8; j++)
                    MMA16816(acc[i][j], af[i], bl[j]);

#pragma unroll
            for (int i = 0; i < 4; i++) {
                const uint32_t byt = (uint32_t)(((arow + i * 16) * ROW_H + kk + acolr) * 2);
                LDMX4(af[i][0], af[i][1], af[i][2], af[i][3],
                      stg + (uint32_t)(TILE_H * 2) + byt);
            }
#pragma unroll
            for (int i = 0; i < 4; i++)
#pragma unroll
                for (int j = 0; j < 8; j++)
                    MMA16816(acc[i][j], af[i], bh[j]);
        }
        __syncthreads();
    }
}

// ---------------------------------------------------------------------------
// Fused Q/K/V projection: grid (8, 64, 3); z=0 Q(hi/lo), z=1 K(round),
// z=2 V(round, transposed).
// ---------------------------------------------------------------------------
__global__ __launch_bounds__(128, 2)
void gemm_qkv(const half* __restrict__ xh,  const half* __restrict__ xl,
              const half* __restrict__ ceh, const half* __restrict__ cel,
              const half* __restrict__ Wq,  const half* __restrict__ Wk,
              const half* __restrict__ Wv,
              const float* __restrict__ bq, const float* __restrict__ bk,
              const float* __restrict__ bv,
              half* __restrict__ Qh,  half* __restrict__ Ql,
              half* __restrict__ Kp,  half* __restrict__ Vt)
{
    extern __shared__ __align__(16) char smem_raw[];
    const int z  = blockIdx.z;
    const int m0 = blockIdx.y * 128;
    const int n0 = blockIdx.x * 128;

    const half *Ah_, *Al_, *B_;
    const float* bias;
    if (z == 0)      { Ah_ = xh;  Al_ = xl;  B_ = Wq; bias = bq; }
    else if (z == 1) { Ah_ = ceh; Al_ = cel; B_ = Wk; bias = bk; }
    else             { Ah_ = ceh; Al_ = cel; B_ = Wv; bias = bv; }

    float acc[4][8][4];
#pragma unroll
    for (int i = 0; i < 4; i++)
#pragma unroll
        for (int j = 0; j < 8; j++)
#pragma unroll
            for (int c = 0; c < 4; c++) acc[i][j][c] = 0.f;

    gemm_core2(Ah_ + (size_t)m0 * C_DIM, Al_ + (size_t)m0 * C_DIM,
               B_ + (size_t)n0 * C_DIM, C_DIM, C_DIM, C_DIM, smem_raw, acc);

    const int tid  = threadIdx.x;
    const int wid  = tid >> 5;
    const int lane = tid & 31;
    const int warp_m = (wid & 1) * 64;
    const int warp_n = (wid >> 1) * 64;
    const int gq = lane >> 2;
    const int tq = lane & 3;

#pragma unroll
    for (int i = 0; i < 4; i++) {
#pragma unroll
        for (int j = 0; j < 8; j++) {
            const int col = n0 + warp_n + j * 8 + tq * 2;
#pragma unroll
            for (int h = 0; h < 2; h++) {
                const int row = m0 + warp_m + i * 16 + gq + h * 8;
                float2 bb = *reinterpret_cast<const float2*>(bias + col);
                float v0 = acc[i][j][2 * h]     + bb.x;
                float v1 = acc[i][j][2 * h + 1] + bb.y;
                if (z == 0) {
                    half h0, h1, l0, l1;
                    split1h(v0, h0, l0); split1h(v1, h1, l1);
                    const size_t idx = (size_t)row * C_DIM + col;
                    *reinterpret_cast<uint32_t*>(Qh + idx) = packh(h0, h1);
                    *reinterpret_cast<uint32_t*>(Ql + idx) = packh(l0, l1);
                } else if (z == 1) {
                    const size_t idx = (size_t)row * C_DIM + col;
                    *reinterpret_cast<uint32_t*>(Kp + idx) =
                        packh(__float2half(v0), __float2half(v1));
                } else {
                    Vt[(size_t)col * M_ALL + row]       = __float2half(v0);
                    Vt[(size_t)(col + 1) * M_ALL + row] = __float2half(v1);
                }
            }
        }
    }
}

// ---------------------------------------------------------------------------
// 2-pass generic GEMM (scores / attnV). OUT_MODE: 0 fp32, 1 split hi/lo.
// ---------------------------------------------------------------------------
template<int OUT_MODE, bool HAS_RES>
__global__ __launch_bounds__(128, 2)
void gemm2(const half* __restrict__ Ah, const half* __restrict__ Al,
           const half* __restrict__ Bg, const float* __restrict__ Rm,
           float* __restrict__ Cf, half* __restrict__ Ch, half* __restrict__ Cl,
           int K, float alpha, int ldA, int ldB, int ldC,
           long long sA, long long sB, long long sC, long long sR)
{
    extern __shared__ __align__(16) char smem_raw[];
    const int z  = blockIdx.z;
    const int m0 = blockIdx.y * 128;
    const int n0 = blockIdx.x * 128;

    float acc[4][8][4];
#pragma unroll
    for (int i = 0; i < 4; i++)
#pragma unroll
        for (int j = 0; j < 8; j++)
#pragma unroll
            for (int c = 0; c < 4; c++) acc[i][j][c] = 0.f;

    gemm_core2(Ah + z * sA + (size_t)m0 * ldA, Al + z * sA + (size_t)m0 * ldA,
               Bg + z * sB + (size_t)n0 * ldB, ldA, ldB, K, smem_raw, acc);

    const int tid  = threadIdx.x;
    const int wid  = tid >> 5;
    const int lane = tid & 31;
    const int warp_m = (wid & 1) * 64;
    const int warp_n = (wid >> 1) * 64;
    const int gq = lane >> 2;
    const int tq = lane & 3;

#pragma unroll
    for (int i = 0; i < 4; i++) {
#pragma unroll
        for (int j = 0; j < 8; j++) {
            const int col = n0 + warp_n + j * 8 + tq * 2;
#pragma unroll
            for (int h = 0; h < 2; h++) {
                const int row = m0 + warp_m + i * 16 + gq + h * 8;
                float v0 = acc[i][j][2 * h]     * alpha;
                float v1 = acc[i][j][2 * h + 1] * alpha;
                if (HAS_RES) {
                    float2 r = *reinterpret_cast<const float2*>(
                        Rm + z * sR + (size_t)row * ldC + col);
                    v0 += r.x; v1 += r.y;
                }
                if (OUT_MODE == 0) {
                    *reinterpret_cast<float2*>(Cf + z * sC + (size_t)row * ldC + col)
                        = make_float2(v0, v1);
                } else {
                    half h0, h1, l0, l1;
                    split1h(v0, h0, l0); split1h(v1, h1, l1);
                    const size_t idx = z * sC + (size_t)row * ldC + col;
                    *reinterpret_cast<uint32_t*>(Ch + idx) = packh(h0, h1);
                    *reinterpret_cast<uint32_t*>(Cl + idx) = packh(l0, l1);
                }
            }
        }
    }
}

// ---------------------------------------------------------------------------
// 3-pass out-projection: out = T@Wo^T + bo (fp32 out).
// ---------------------------------------------------------------------------
__global__ __launch_bounds__(128, 2)
void gemm_out(const half* __restrict__ Th, const half* __restrict__ Tl,
              const half* __restrict__ Woh, const half* __restrict__ Wol,
              const float* __restrict__ bo, float* __restrict__ out)
{
    extern __shared__ __align__(16) char smem_raw[];
    const int m0 = blockIdx.y * 128;
    const int n0 = blockIdx.x * 128;

    float acc[4][8][4];
#pragma unroll
    for (int i = 0; i < 4; i++)
#pragma unroll
        for (int j = 0; j < 8; j++)
#pragma unroll
            for (int c = 0; c < 4; c++) acc[i][j][c] = 0.f;

    gemm_core3(Th + (size_t)m0 * C_DIM, Tl + (size_t)m0 * C_DIM,
               Woh + (size_t)n0 * C_DIM, Wol + (size_t)n0 * C_DIM,
               C_DIM, C_DIM, C_DIM, smem_raw, acc);

    const int tid  = threadIdx.x;
    const int wid  = tid >> 5;
    const int lane = tid & 31;
    const int warp_m = (wid & 1) * 64;
    const int warp_n = (wid >> 1) * 64;
    const int gq = lane >> 2;
    const int tq = lane & 3;

#pragma unroll
    for (int i = 0; i < 4; i++) {
#pragma unroll
        for (int j = 0; j < 8; j++) {
            const int col = n0 + warp_n + j * 8 + tq * 2;
#pragma unroll
            for (int h = 0; h < 2; h++) {
                const int row = m0 + warp_m + i * 16 + gq + h * 8;
                float2 bb = *reinterpret_cast<const float2*>(bo + col);
                *reinterpret_cast<float2*>(out + (size_t)row * C_DIM + col) =
                    make_float2(acc[i][j][2 * h] + bb.x, acc[i][j][2 * h + 1] + bb.y);
            }
        }
    }
}

// ---------------------------------------------------------------------------
// Row softmax (2048/row) -> fp16 hi/lo probability planes.
// ---------------------------------------------------------------------------
__global__ __launch_bounds__(256)
void softmax2048(const float* __restrict__ S, half* __restrict__ Ph,
                 half* __restrict__ Pl)
{
    const long long row = blockIdx.x;
    const float* p = S + row * 2048;
    const int tid = threadIdx.x;
    const int w = tid >> 5, l = tid & 31;

    float v[8];
    {
        float4 x0 = *reinterpret_cast<const float4*>(p + tid * 8);
        float4 x1 = *reinterpret_cast<const float4*>(p + tid * 8 + 4);
        v[0] = x0.x; v[1] = x0.y; v[2] = x0.z; v[3] = x0.w;
        v[4] = x1.x; v[5] = x1.y; v[6] = x1.z; v[7] = x1.w;
    }
    __shared__ float smax[8], ssum[8];

    float m = v[0];
#pragma unroll
    for (int j = 1; j < 8; j++) m = fmaxf(m, v[j]);
#pragma unroll
    for (int off = 16; off >= 1; off >>= 1)
        m = fmaxf(m, __shfl_xor_sync(0xffffffffu, m, off));
    if (l == 0) smax[w] = m;
    __syncthreads();
    float bm = smax[0];
#pragma unroll
    for (int j = 1; j < 8; j++) bm = fmaxf(bm, smax[j]);

    float s = 0.f;
#pragma unroll
    for (int j = 0; j < 8; j++) { v[j] = expf(v[j] - bm); s += v[j]; }
#pragma unroll
    for (int off = 16; off >= 1; off >>= 1)
        s += __shfl_xor_sync(0xffffffffu, s, off);
    if (l == 0) ssum[w] = s;
    __syncthreads();
    float tot = ssum[0];
#pragma unroll
    for (int j = 1; j < 8; j++) tot += ssum[j];

    const float inv = 1.f / tot;
    half hh[8], ll[8];
#pragma unroll
    for (int j = 0; j < 8; j++) { v[j] *= inv; split1h(v[j], hh[j], ll[j]); }

    const long long ob = row * 2048 + tid * 8;
    *reinterpret_cast<uint2*>(Ph + ob) =
        make_uint2(packh(hh[0], hh[1]), packh(hh[2], hh[3]));
    *reinterpret_cast<uint2*>(Ph + ob + 4) =
        make_uint2(packh(hh[4], hh[5]), packh(hh[6], hh[7]));
    *reinterpret_cast<uint2*>(Pl + ob) =
        make_uint2(packh(ll[0], ll[1]), packh(ll[2], ll[3]));
    *reinterpret_cast<uint2*>(Pl + ob + 4) =
        make_uint2(packh(ll[4], ll[5]), packh(ll[6], ll[7]));
}

// ---------------------------------------------------------------------------
extern "C" void kernel_launch(void* const* d_in, const int* in_sizes, int n_in,
                              void* d_out, int out_size)
{
    (void)in_sizes; (void)n_in; (void)out_size;
    const float* x  = (const float*)d_in[0];
    const float* ce = (const float*)d_in[1];
    const float* Wq = (const float*)d_in[2];
    const float* bq = (const float*)d_in[3];
    const float* Wk = (const float*)d_in[4];
    const float* bk = (const float*)d_in[5];
    const float* Wv = (const float*)d_in[6];
    const float* bv = (const float*)d_in[7];
    const float* Wo = (const float*)d_in[8];
    const float* bo = (const float*)d_in[9];
    float* out = (float*)d_out;

    float* S;
    half *xh, *xl, *ceh, *cel, *Wq1, *Wk1, *Wv1, *Woh, *Wol;
    half *Qh, *Ql, *Kp, *Vt, *Ph, *Pl, *Th, *Tl;
    cudaGetSymbolAddress((void**)&S,   g_S);
    cudaGetSymbolAddress((void**)&xh,  g_xh);  cudaGetSymbolAddress((void**)&xl,  g_xl);
    cudaGetSymbolAddress((void**)&ceh, g_ceh); cudaGetSymbolAddress((void**)&cel, g_cel);
    cudaGetSymbolAddress((void**)&Wq1, g_Wq);  cudaGetSymbolAddress((void**)&Wk1, g_Wk);
    cudaGetSymbolAddress((void**)&Wv1, g_Wv);
    cudaGetSymbolAddress((void**)&Woh, g_Woh); cudaGetSymbolAddress((void**)&Wol, g_Wol);
    cudaGetSymbolAddress((void**)&Qh,  g_Qh);  cudaGetSymbolAddress((void**)&Ql,  g_Ql);
    cudaGetSymbolAddress((void**)&Kp,  g_K);   cudaGetSymbolAddress((void**)&Vt,  g_Vt);
    cudaGetSymbolAddress((void**)&Ph,  g_Ph);  cudaGetSymbolAddress((void**)&Pl,  g_Pl);
    cudaGetSymbolAddress((void**)&Th,  g_Th);  cudaGetSymbolAddress((void**)&Tl,  g_Tl);

    cudaFuncSetAttribute(gemm_qkv, cudaFuncAttributeMaxDynamicSharedMemorySize, SMEM2);
    cudaFuncSetAttribute(gemm2<0, false>, cudaFuncAttributeMaxDynamicSharedMemorySize, SMEM2);
    cudaFuncSetAttribute(gemm2<1, true >, cudaFuncAttributeMaxDynamicSharedMemorySize, SMEM2);
    cudaFuncSetAttribute(gemm_out, cudaFuncAttributeMaxDynamicSharedMemorySize, SMEM3);

    // fused pre-split (20480 blocks of 1024 floats)
    split_all<<<20480, 256>>>(
        (const float4*)x, (const float4*)ce, (const float4*)Wq,
        (const float4*)Wk, (const float4*)Wv, (const float4*)Wo,
        (uint2*)xh, (uint2*)xl, (uint2*)ceh, (uint2*)cel,
        (uint2*)Wq1, (uint2*)Wk1, (uint2*)Wv1, (uint2*)Woh, (uint2*)Wol);

    const long long sQ = (long long)S_DIM * C_DIM;
    const long long sS = (long long)S_DIM * S_DIM;

    // fused Q/K/V projections (one launch, 1536 CTAs)
    gemm_qkv<<<dim3(8, 64, 3), 128, SMEM2>>>(
        xh, xl, ceh, cel, Wq1, Wk1, Wv1, bq, bk, bv, Qh, Ql, Kp, Vt);

    // scores: per-batch Q @ K^T / 32 -> fp32 S   (A = Q split, B = K rounded)
    gemm2<0, false><<<dim3(16, 16, B_DIM), 128, SMEM2>>>(
        Qh, Ql, Kp, nullptr, S, nullptr, nullptr,
        C_DIM, 0.03125f, C_DIM, C_DIM, S_DIM, sQ, sQ, sS, 0);

    softmax2048<<<M_ALL, 256>>>(S, Ph, Pl);

    // attended + residual -> split fp16 T  (A = P split, B = Vt rounded)
    gemm2<1, true><<<dim3(8, 16, B_DIM), 128, SMEM2>>>(
        Ph, Pl, Vt, x, nullptr, Th, Tl,
        S_DIM, 1.f, S_DIM, M_ALL, C_DIM, sS, S_DIM, sQ, sQ);

    // output projection (3-pass, fp32 out)
    gemm_out<<<dim3(8, 64, 1), 128, SMEM3>>>(Th, Tl, Woh, Wol, bo, out);
}

// round 10
// speedup vs baseline: 2.5990x; 1.6502x over previous
#include <cuda_runtime.h>
#include <cuda_fp16.h>
#include <cstdint>
#include <math.h>

// ---------------------------------------------------------------------------
// SpatialTransformer via mma.sync fp16 (HMMA).
// Round 10: 1-pass fp16 GEMMs (both operands rounded) for qkv/scores/attnV;
// 2-pass (T split, Wo rounded) out-projection. 3-stage cp.async ring,
// 64x64 warp tiles, 128 thr, 2 CTAs/SM.
// ---------------------------------------------------------------------------

#define B_DIM 4
#define S_DIM 2048
#define C_DIM 1024
#define M_ALL (B_DIM * S_DIM)   // 8192

__device__ float g_S[(long long)B_DIM * S_DIM * S_DIM];  // scores, 64 MB
__device__ half g_x16[M_ALL * C_DIM], g_ce16[M_ALL * C_DIM];
__device__ half g_Wq16[C_DIM * C_DIM], g_Wk16[C_DIM * C_DIM];
__device__ half g_Wv16[C_DIM * C_DIM], g_Wo16[C_DIM * C_DIM];
__device__ half g_Q16[M_ALL * C_DIM], g_K16[M_ALL * C_DIM];
__device__ half g_Vt16[C_DIM * M_ALL];                      // V^T [C][B*S]
__device__ half g_P16[(long long)B_DIM * S_DIM * S_DIM];
__device__ half g_Th[M_ALL * C_DIM], g_Tl[M_ALL * C_DIM];   // split T

__device__ __forceinline__ uint32_t smem_u32(const void* p) {
    uint32_t a;
    asm("{ .reg .u64 t; cvta.to.shared.u64 t, %1; cvt.u32.u64 %0, t; }"
        : "=r"(a) : "l"(p));
    return a;
}

#define LDMX4(r0, r1, r2, r3, addr) \
    asm volatile("ldmatrix.sync.aligned.m8n8.x4.shared.b16 {%0,%1,%2,%3}, [%4];" \
                 : "=r"(r0), "=r"(r1), "=r"(r2), "=r"(r3) : "r"(addr))
#define MMA16816(d, a, b) \
    asm volatile("mma.sync.aligned.m16n8k16.row.col.f32.f16.f16.f32 " \
                 "{%0,%1,%2,%3}, {%4,%5,%6,%7}, {%8,%9}, {%0,%1,%2,%3};" \
                 : "+f"((d)[0]), "+f"((d)[1]), "+f"((d)[2]), "+f"((d)[3]) \
                 : "r"((a)[0]), "r"((a)[1]), "r"((a)[2]), "r"((a)[3]), \
                   "r"((b)[0]), "r"((b)[1]))
#define CP_ASYNC16(dst, src) \
    asm volatile("cp.async.cg.shared.global [%0], [%1], 16;" \
                 :: "r"(dst), "l"(src) : "memory")
#define CP_COMMIT() asm volatile("cp.async.commit_group;" ::: "memory")

#define KT        32
#define ROW_H     40
#define TILE_H    (128 * ROW_H)          // halves (5120)
// 1-pass core: 2 tiles/stage (A, B), 3-stage ring
#define STAGE1_H  (2 * TILE_H)
#define SMEM1     (3 * STAGE1_H * 2)     // 61440 B
// 2-pass core: 3 tiles/stage (Ah, Al, B), 3-stage ring
#define STAGE2_H  (3 * TILE_H)
#define SMEM2     (3 * STAGE2_H * 2)     // 92160 B

__device__ __forceinline__ uint32_t packh(half a, half b) {
    __half2 t; t.x = a; t.y = b;
    return *reinterpret_cast<uint32_t*>(&t);
}
__device__ __forceinline__ void split1h(float v, half& h, half& l) {
    h = __float2half(v);
    l = __float2half(v - __half2float(h));
}

// ---------------------------------------------------------------------------
// Fused rounding pass: all six fp32 tensors -> fp16.
// Block segments of 1024 floats: x 8192, ce 8192, Wq/Wk/Wv/Wo 1024 each.
// ---------------------------------------------------------------------------
__global__ __launch_bounds__(256)
void round_all(const float4* __restrict__ x,  const float4* __restrict__ ce,
               const float4* __restrict__ Wq, const float4* __restrict__ Wk,
               const float4* __restrict__ Wv, const float4* __restrict__ Wo,
               uint2* __restrict__ x16,  uint2* __restrict__ ce16,
               uint2* __restrict__ Wq16, uint2* __restrict__ Wk16,
               uint2* __restrict__ Wv16, uint2* __restrict__ Wo16)
{
    const int b = blockIdx.x;
    const float4* in; uint2* o; int lb;
    if (b < 8192)       { in = x;  o = x16;  lb = b; }
    else if (b < 16384) { in = ce; o = ce16; lb = b - 8192; }
    else if (b < 17408) { in = Wq; o = Wq16; lb = b - 16384; }
    else if (b < 18432) { in = Wk; o = Wk16; lb = b - 17408; }
    else if (b < 19456) { in = Wv; o = Wv16; lb = b - 18432; }
    else                { in = Wo; o = Wo16; lb = b - 19456; }

    const int i = lb * 256 + threadIdx.x;
    float4 v = in[i];
    o[i] = make_uint2(packh(__float2half(v.x), __float2half(v.y)),
                      packh(__float2half(v.z), __float2half(v.w)));
}

// ---------------------------------------------------------------------------
// 1-pass mainloop: acc += A@B^T. 2 smem tiles/stage, 3-stage ring.
// ---------------------------------------------------------------------------
__device__ __forceinline__ void gemm_core1(
    const half* __restrict__ Ag, const half* __restrict__ Bg,
    int ldA, int ldB, int K, char* smem_raw, float acc[4][8][4])
{
    const uint32_t sm_base = smem_u32(smem_raw);
    const int tid  = threadIdx.x;
    const int lane = tid & 31;
    const int wid  = tid >> 5;

    const int warp_m = (wid & 1) * 64;
    const int warp_n = (wid >> 1) * 64;

    const int r0 = tid >> 2;
    const int kc = (tid & 3) * 8;

    const int arow  = warp_m + (lane & 15);
    const int acolr = (lane >> 4) << 3;
    const int brow_off = ((lane >> 4) << 3) + (lane & 7);
    const int bcolr = lane & 8;

    const int NK = K >> 5;

    auto load_stage = [&](int buf, int kt) {
        const uint32_t sbase = sm_base + (uint32_t)(buf * STAGE1_H) * 2;
        const int kk = kt * KT + kc;
#pragma unroll
        for (int rr = 0; rr < 4; rr++) {
            const int row = r0 + rr * 32;
            const uint32_t so = (uint32_t)(row * ROW_H + kc) * 2;
            CP_ASYNC16(sbase + so,                          Ag + (size_t)row * ldA + kk);
            CP_ASYNC16(sbase + (uint32_t)(TILE_H * 2) + so, Bg + (size_t)row * ldB + kk);
        }
    };

    load_stage(0, 0);
    CP_COMMIT();
    load_stage(1, 1);
    CP_COMMIT();

    for (int kt = 0; kt < NK; ++kt) {
        if (kt + 2 < NK) {
            load_stage((kt + 2) % 3, kt + 2);
            CP_COMMIT();
        }
        const int rem = NK - 1 - kt;
        if (rem >= 2)      asm volatile("cp.async.wait_group 2;" ::: "memory");
        else if (rem == 1) asm volatile("cp.async.wait_group 1;" ::: "memory");
        else               asm volatile("cp.async.wait_group 0;" ::: "memory");
        __syncthreads();

        const uint32_t stg = sm_base + (uint32_t)((kt % 3) * STAGE1_H) * 2;
#pragma unroll
        for (int half_ = 0; half_ < 2; ++half_) {
            const int kk = half_ * 16;
            uint32_t af[4][4];
            uint32_t bb[8][2];

#pragma unroll
            for (int i = 0; i < 4; i++) {
                const uint32_t byt = (uint32_t)(((arow + i * 16) * ROW_H + kk + acolr) * 2);
                LDMX4(af[i][0], af[i][1], af[i][2], af[i][3], stg + byt);
            }
#pragma unroll
            for (int jj = 0; jj < 8; jj += 2) {
                const uint32_t byt =
                    (uint32_t)(((warp_n + jj * 8 + brow_off) * ROW_H + kk + bcolr) * 2);
                LDMX4(bb[jj][0], bb[jj][1], bb[jj + 1][0], bb[jj + 1][1],
                      stg + (uint32_t)(TILE_H * 2) + byt);
            }
#pragma unroll
            for (int i = 0; i < 4; i++)
#pragma unroll
                for (int j = 0; j < 8; j++)
                    MMA16816(acc[i][j], af[i], bb[j]);
        }
        __syncthreads();
    }
}

// ---------------------------------------------------------------------------
// 2-pass mainloop (outproj): acc += (Ah+Al)@B^T. 3 tiles/stage, 3-stage ring.
// ---------------------------------------------------------------------------
__device__ __forceinline__ void gemm_core2(
    const half* __restrict__ Agh, const half* __restrict__ Agl,
    const half* __restrict__ Bg,
    int ldA, int ldB, int K, char* smem_raw, float acc[4][8][4])
{
    const uint32_t sm_base = smem_u32(smem_raw);
    const int tid  = threadIdx.x;
    const int lane = tid & 31;
    const int wid  = tid >> 5;

    const int warp_m = (wid & 1) * 64;
    const int warp_n = (wid >> 1) * 64;

    const int r0 = tid >> 2;
    const int kc = (tid & 3) * 8;

    const int arow  = warp_m + (lane & 15);
    const int acolr = (lane >> 4) << 3;
    const int brow_off = ((lane >> 4) << 3) + (lane & 7);
    const int bcolr = lane & 8;

    const int NK = K >> 5;

    auto load_stage = [&](int buf, int kt) {
        const uint32_t sbase = sm_base + (uint32_t)(buf * STAGE2_H) * 2;
        const int kk = kt * KT + kc;
#pragma unroll
        for (int rr = 0; rr < 4; rr++) {
            const int row = r0 + rr * 32;
            const uint32_t so = (uint32_t)(row * ROW_H + kc) * 2;
            CP_ASYNC16(sbase + so,                              Agh + (size_t)row * ldA + kk);
            CP_ASYNC16(sbase + (uint32_t)(TILE_H * 2) + so,     Agl + (size_t)row * ldA + kk);
            CP_ASYNC16(sbase + (uint32_t)(2 * TILE_H * 2) + so, Bg  + (size_t)row * ldB + kk);
        }
    };

    load_stage(0, 0);
    CP_COMMIT();
    load_stage(1, 1);
    CP_COMMIT();

    for (int kt = 0; kt < NK; ++kt) {
        if (kt + 2 < NK) {
            load_stage((kt + 2) % 3, kt + 2);
            CP_COMMIT();
        }
        const int rem = NK - 1 - kt;
        if (rem >= 2)      asm volatile("cp.async.wait_group 2;" ::: "memory");
        else if (rem == 1) asm volatile("cp.async.wait_group 1;" ::: "memory");
        else               asm volatile("cp.async.wait_group 0;" ::: "memory");
        __syncthreads();

        const uint32_t stg = sm_base + (uint32_t)((kt % 3) * STAGE2_H) * 2;
#pragma unroll
        for (int half_ = 0; half_ < 2; ++half_) {
            const int kk = half_ * 16;
            uint32_t af[4][4];
            uint32_t bb[8][2];

#pragma unroll
            for (int i = 0; i < 4; i++) {
                const uint32_t byt = (uint32_t)(((arow + i * 16) * ROW_H + kk + acolr) * 2);
                LDMX4(af[i][0], af[i][1], af[i][2], af[i][3], stg + byt);
            }
#pragma unroll
            for (int jj = 0; jj < 8; jj += 2) {
                const uint32_t byt =
                    (uint32_t)(((warp_n + jj * 8 + brow_off) * ROW_H + kk + bcolr) * 2);
                LDMX4(bb[jj][0], bb[jj][1], bb[jj + 1][0], bb[jj + 1][1],
                      stg + (uint32_t)(2 * TILE_H * 2) + byt);
            }
#pragma unroll
            for (int i = 0; i < 4; i++)
#pragma unroll
                for (int j = 0; j < 8; j++)
                    MMA16816(acc[i][j], af[i], bb[j]);

#pragma unroll
            for (int i = 0; i < 4; i++) {
                const uint32_t byt = (uint32_t)(((arow + i * 16) * ROW_H + kk + acolr) * 2);
                LDMX4(af[i][0], af[i][1], af[i][2], af[i][3],
                      stg + (uint32_t)(TILE_H * 2) + byt);
            }
#pragma unroll
            for (int i = 0; i < 4; i++)
#pragma unroll
                for (int j = 0; j < 8; j++)
                    MMA16816(acc[i][j], af[i], bb[j]);
        }
        __syncthreads();
    }
}

// ---------------------------------------------------------------------------
// Fused Q/K/V projection (1-pass): grid (8, 64, 3).
// z=0 Q, z=1 K, z=2 V (transposed). All outputs fp16 rounded.
// ---------------------------------------------------------------------------
__global__ __launch_bounds__(128, 2)
void gemm_qkv(const half* __restrict__ x16, const half* __restrict__ ce16,
              const half* __restrict__ Wq16, const half* __restrict__ Wk16,
              const half* __restrict__ Wv16,
              const float* __restrict__ bq, const float* __restrict__ bk,
              const float* __restrict__ bv,
              half* __restrict__ Q16, half* __restrict__ K16,
              half* __restrict__ Vt16)
{
    extern __shared__ __align__(16) char smem_raw[];
    const int z  = blockIdx.z;
    const int m0 = blockIdx.y * 128;
    const int n0 = blockIdx.x * 128;

    const half *A_, *B_;
    const float* bias;
    if (z == 0)      { A_ = x16;  B_ = Wq16; bias = bq; }
    else if (z == 1) { A_ = ce16; B_ = Wk16; bias = bk; }
    else             { A_ = ce16; B_ = Wv16; bias = bv; }

    float acc[4][8][4];
#pragma unroll
    for (int i = 0; i < 4; i++)
#pragma unroll
        for (int j = 0; j < 8; j++)
#pragma unroll
            for (int c = 0; c < 4; c++) acc[i][j][c] = 0.f;

    gemm_core1(A_ + (size_t)m0 * C_DIM, B_ + (size_t)n0 * C_DIM,
               C_DIM, C_DIM, C_DIM, smem_raw, acc);

    const int tid  = threadIdx.x;
    const int wid  = tid >> 5;
    const int lane = tid & 31;
    const int warp_m = (wid & 1) * 64;
    const int warp_n = (wid >> 1) * 64;
    const int gq = lane >> 2;
    const int tq = lane & 3;

#pragma unroll
    for (int i = 0; i < 4; i++) {
#pragma unroll
        for (int j = 0; j < 8; j++) {
            const int col = n0 + warp_n + j * 8 + tq * 2;
#pragma unroll
            for (int h = 0; h < 2; h++) {
                const int row = m0 + warp_m + i * 16 + gq + h * 8;
                float2 bb = *reinterpret_cast<const float2*>(bias + col);
                float v0 = acc[i][j][2 * h]     + bb.x;
                float v1 = acc[i][j][2 * h + 1] + bb.y;
                if (z == 0) {
                    *reinterpret_cast<uint32_t*>(Q16 + (size_t)row * C_DIM + col) =
                        packh(__float2half(v0), __float2half(v1));
                } else if (z == 1) {
                    *reinterpret_cast<uint32_t*>(K16 + (size_t)row * C_DIM + col) =
                        packh(__float2half(v0), __float2half(v1));
                } else {
                    Vt16[(size_t)col * M_ALL + row]       = __float2half(v0);
                    Vt16[(size_t)(col + 1) * M_ALL + row] = __float2half(v1);
                }
            }
        }
    }
}

// ---------------------------------------------------------------------------
// 1-pass generic GEMM. OUT_MODE: 0 fp32 out, 1 split fp16 hi/lo out.
// ---------------------------------------------------------------------------
template<int OUT_MODE, bool HAS_RES>
__global__ __launch_bounds__(128, 2)
void gemm1(const half* __restrict__ Ag, const half* __restrict__ Bg,
           const float* __restrict__ Rm,
           float* __restrict__ Cf, half* __restrict__ Ch, half* __restrict__ Cl,
           int K, float alpha, int ldA, int ldB, int ldC,
           long long sA, long long sB, long long sC, long long sR)
{
    extern __shared__ __align__(16) char smem_raw[];
    const int z  = blockIdx.z;
    const int m0 = blockIdx.y * 128;
    const int n0 = blockIdx.x * 128;

    float acc[4][8][4];
#pragma unroll
    for (int i = 0; i < 4; i++)
#pragma unroll
        for (int j = 0; j < 8; j++)
#pragma unroll
            for (int c = 0; c < 4; c++) acc[i][j][c] = 0.f;

    gemm_core1(Ag + z * sA + (size_t)m0 * ldA, Bg + z * sB + (size_t)n0 * ldB,
               ldA, ldB, K, smem_raw, acc);

    const int tid  = threadIdx.x;
    const int wid  = tid >> 5;
    const int lane = tid & 31;
    const int warp_m = (wid & 1) * 64;
    const int warp_n = (wid >> 1) * 64;
    const int gq = lane >> 2;
    const int tq = lane & 3;

#pragma unroll
    for (int i = 0; i < 4; i++) {
#pragma unroll
        for (int j = 0; j < 8; j++) {
            const int col = n0 + warp_n + j * 8 + tq * 2;
#pragma unroll
            for (int h = 0; h < 2; h++) {
                const int row = m0 + warp_m + i * 16 + gq + h * 8;
                float v0 = acc[i][j][2 * h]     * alpha;
                float v1 = acc[i][j][2 * h + 1] * alpha;
                if (HAS_RES) {
                    float2 r = *reinterpret_cast<const float2*>(
                        Rm + z * sR + (size_t)row * ldC + col);
                    v0 += r.x; v1 += r.y;
                }
                if (OUT_MODE == 0) {
                    *reinterpret_cast<float2*>(Cf + z * sC + (size_t)row * ldC + col)
                        = make_float2(v0, v1);
                } else {
                    half h0, h1, l0, l1;
                    split1h(v0, h0, l0); split1h(v1, h1, l1);
                    const size_t idx = z * sC + (size_t)row * ldC + col;
                    *reinterpret_cast<uint32_t*>(Ch + idx) = packh(h0, h1);
                    *reinterpret_cast<uint32_t*>(Cl + idx) = packh(l0, l1);
                }
            }
        }
    }
}

// ---------------------------------------------------------------------------
// 2-pass out-projection: out = (Th+Tl)@Wo^T + bo (fp32 out).
// ---------------------------------------------------------------------------
__global__ __launch_bounds__(128, 2)
void gemm_out(const half* __restrict__ Th, const half* __restrict__ Tl,
              const half* __restrict__ Wo16,
              const float* __restrict__ bo, float* __restrict__ out)
{
    extern __shared__ __align__(16) char smem_raw[];
    const int m0 = blockIdx.y * 128;
    const int n0 = blockIdx.x * 128;

    float acc[4][8][4];
#pragma unroll
    for (int i = 0; i < 4; i++)
#pragma unroll
        for (int j = 0; j < 8; j++)
#pragma unroll
            for (int c = 0; c < 4; c++) acc[i][j][c] = 0.f;

    gemm_core2(Th + (size_t)m0 * C_DIM, Tl + (size_t)m0 * C_DIM,
               Wo16 + (size_t)n0 * C_DIM, C_DIM, C_DIM, C_DIM, smem_raw, acc);

    const int tid  = threadIdx.x;
    const int wid  = tid >> 5;
    const int lane = tid & 31;
    const int warp_m = (wid & 1) * 64;
    const int warp_n = (wid >> 1) * 64;
    const int gq = lane >> 2;
    const int tq = lane & 3;

#pragma unroll
    for (int i = 0; i < 4; i++) {
#pragma unroll
        for (int j = 0; j < 8; j++) {
            const int col = n0 + warp_n + j * 8 + tq * 2;
#pragma unroll
            for (int h = 0; h < 2; h++) {
                const int row = m0 + warp_m + i * 16 + gq + h * 8;
                float2 bb = *reinterpret_cast<const float2*>(bo + col);
                *reinterpret_cast<float2*>(out + (size_t)row * C_DIM + col) =
                    make_float2(acc[i][j][2 * h] + bb.x, acc[i][j][2 * h + 1] + bb.y);
            }
        }
    }
}

// ---------------------------------------------------------------------------
// Row softmax (2048/row) -> fp16 probabilities (single plane).
// ---------------------------------------------------------------------------
__global__ __launch_bounds__(256)
void softmax2048(const float* __restrict__ S, half* __restrict__ P)
{
    const long long row = blockIdx.x;
    const float* p = S + row * 2048;
    const int tid = threadIdx.x;
    const int w = tid >> 5, l = tid & 31;

    float v[8];
    {
        float4 x0 = *reinterpret_cast<const float4*>(p + tid * 8);
        float4 x1 = *reinterpret_cast<const float4*>(p + tid * 8 + 4);
        v[0] = x0.x; v[1] = x0.y; v[2] = x0.z; v[3] = x0.w;
        v[4] = x1.x; v[5] = x1.y; v[6] = x1.z; v[7] = x1.w;
    }
    __shared__ float smax[8], ssum[8];

    float m = v[0];
#pragma unroll
    for (int j = 1; j < 8; j++) m = fmaxf(m, v[j]);
#pragma unroll
    for (int off = 16; off >= 1; off >>= 1)
        m = fmaxf(m, __shfl_xor_sync(0xffffffffu, m, off));
    if (l == 0) smax[w] = m;
    __syncthreads();
    float bm = smax[0];
#pragma unroll
    for (int j = 1; j < 8; j++) bm = fmaxf(bm, smax[j]);

    float s = 0.f;
#pragma unroll
    for (int j = 0; j < 8; j++) { v[j] = expf(v[j] - bm); s += v[j]; }
#pragma unroll
    for (int off = 16; off >= 1; off >>= 1)
        s += __shfl_xor_sync(0xffffffffu, s, off);
    if (l == 0) ssum[w] = s;
    __syncthreads();
    float tot = ssum[0];
#pragma unroll
    for (int j = 1; j < 8; j++) tot += ssum[j];

    const float inv = 1.f / tot;
    half hh[8];
#pragma unroll
    for (int j = 0; j < 8; j++) hh[j] = __float2half(v[j] * inv);

    const long long ob = row * 2048 + tid * 8;
    *reinterpret_cast<uint2*>(P + ob) =
        make_uint2(packh(hh[0], hh[1]), packh(hh[2], hh[3]));
    *reinterpret_cast<uint2*>(P + ob + 4) =
        make_uint2(packh(hh[4], hh[5]), packh(hh[6], hh[7]));
}

// ---------------------------------------------------------------------------
extern "C" void kernel_launch(void* const* d_in, const int* in_sizes, int n_in,
                              void* d_out, int out_size)
{
    (void)in_sizes; (void)n_in; (void)out_size;
    const float* x  = (const float*)d_in[0];
    const float* ce = (const float*)d_in[1];
    const float* Wq = (const float*)d_in[2];
    const float* bq = (const float*)d_in[3];
    const float* Wk = (const float*)d_in[4];
    const float* bk = (const float*)d_in[5];
    const float* Wv = (const float*)d_in[6];
    const float* bv = (const float*)d_in[7];
    const float* Wo = (const float*)d_in[8];
    const float* bo = (const float*)d_in[9];
    float* out = (float*)d_out;

    float* S;
    half *x16, *ce16, *Wq16, *Wk16, *Wv16, *Wo16;
    half *Q16, *K16, *Vt16, *P16, *Th, *Tl;
    cudaGetSymbolAddress((void**)&S,    g_S);
    cudaGetSymbolAddress((void**)&x16,  g_x16);  cudaGetSymbolAddress((void**)&ce16, g_ce16);
    cudaGetSymbolAddress((void**)&Wq16, g_Wq16); cudaGetSymbolAddress((void**)&Wk16, g_Wk16);
    cudaGetSymbolAddress((void**)&Wv16, g_Wv16); cudaGetSymbolAddress((void**)&Wo16, g_Wo16);
    cudaGetSymbolAddress((void**)&Q16,  g_Q16);  cudaGetSymbolAddress((void**)&K16,  g_K16);
    cudaGetSymbolAddress((void**)&Vt16, g_Vt16); cudaGetSymbolAddress((void**)&P16,  g_P16);
    cudaGetSymbolAddress((void**)&Th,   g_Th);   cudaGetSymbolAddress((void**)&Tl,   g_Tl);

    cudaFuncSetAttribute(gemm_qkv, cudaFuncAttributeMaxDynamicSharedMemorySize, SMEM1);
    cudaFuncSetAttribute(gemm1<0, false>, cudaFuncAttributeMaxDynamicSharedMemorySize, SMEM1);
    cudaFuncSetAttribute(gemm1<1, true >, cudaFuncAttributeMaxDynamicSharedMemorySize, SMEM1);
    cudaFuncSetAttribute(gemm_out, cudaFuncAttributeMaxDynamicSharedMemorySize, SMEM2);

    // fused rounding pass (20480 blocks of 1024 floats)
    round_all<<<20480, 256>>>(
        (const float4*)x, (const float4*)ce, (const float4*)Wq,
        (const float4*)Wk, (const float4*)Wv, (const float4*)Wo,
        (uint2*)x16, (uint2*)ce16, (uint2*)Wq16, (uint2*)Wk16,
        (uint2*)Wv16, (uint2*)Wo16);

    const long long sQ = (long long)S_DIM * C_DIM;
    const long long sS = (long long)S_DIM * S_DIM;

    // fused Q/K/V projections (one launch, 1536 CTAs, 1-pass)
    gemm_qkv<<<dim3(8, 64, 3), 128, SMEM1>>>(
        x16, ce16, Wq16, Wk16, Wv16, bq, bk, bv, Q16, K16, Vt16);

    // scores: per-batch Q @ K^T / 32 -> fp32 S (1-pass)
    gemm1<0, false><<<dim3(16, 16, B_DIM), 128, SMEM1>>>(
        Q16, K16, nullptr, S, nullptr, nullptr,
        C_DIM, 0.03125f, C_DIM, C_DIM, S_DIM, sQ, sQ, sS, 0);

    softmax2048<<<M_ALL, 256>>>(S, P16);

    // attended + residual -> split fp16 T (1-pass)
    gemm1<1, true><<<dim3(8, 16, B_DIM), 128, SMEM1>>>(
        P16, Vt16, x, nullptr, Th, Tl,
        S_DIM, 1.f, S_DIM, M_ALL, C_DIM, sS, S_DIM, sQ, sQ);

    // output projection (2-pass: T split, Wo rounded; fp32 out)
    gemm_out<<<dim3(8, 64, 1), 128, SMEM2>>>(Th, Tl, Wo16, bo, out);
}

// round 11
// speedup vs baseline: 2.5993x; 1.0001x over previous
#include <cuda_runtime.h>
#include <cuda_fp16.h>
#include <cstdint>
#include <math.h>

// ---------------------------------------------------------------------------
// SpatialTransformer via mma.sync fp16 (HMMA).
// Round 11: same math as round 10 (1-pass fp16 qkv/scores/attnV; 2-pass
// outproj), but 1-pass GEMMs run 3 CTAs/SM (12 warps/SM) for latency hiding.
// ---------------------------------------------------------------------------

#define B_DIM 4
#define S_DIM 2048
#define C_DIM 1024
#define M_ALL (B_DIM * S_DIM)   // 8192

__device__ float g_S[(long long)B_DIM * S_DIM * S_DIM];  // scores, 64 MB
__device__ half g_x16[M_ALL * C_DIM], g_ce16[M_ALL * C_DIM];
__device__ half g_Wq16[C_DIM * C_DIM], g_Wk16[C_DIM * C_DIM];
__device__ half g_Wv16[C_DIM * C_DIM], g_Wo16[C_DIM * C_DIM];
__device__ half g_Q16[M_ALL * C_DIM], g_K16[M_ALL * C_DIM];
__device__ half g_Vt16[C_DIM * M_ALL];                      // V^T [C][B*S]
__device__ half g_P16[(long long)B_DIM * S_DIM * S_DIM];
__device__ half g_Th[M_ALL * C_DIM], g_Tl[M_ALL * C_DIM];   // split T

__device__ __forceinline__ uint32_t smem_u32(const void* p) {
    uint32_t a;
    asm("{ .reg .u64 t; cvta.to.shared.u64 t, %1; cvt.u32.u64 %0, t; }"
        : "=r"(a) : "l"(p));
    return a;
}

#define LDMX4(r0, r1, r2, r3, addr) \
    asm volatile("ldmatrix.sync.aligned.m8n8.x4.shared.b16 {%0,%1,%2,%3}, [%4];" \
                 : "=r"(r0), "=r"(r1), "=r"(r2), "=r"(r3) : "r"(addr))
#define MMA16816(d, a, b) \
    asm volatile("mma.sync.aligned.m16n8k16.row.col.f32.f16.f16.f32 " \
                 "{%0,%1,%2,%3}, {%4,%5,%6,%7}, {%8,%9}, {%0,%1,%2,%3};" \
                 : "+f"((d)[0]), "+f"((d)[1]), "+f"((d)[2]), "+f"((d)[3]) \
                 : "r"((a)[0]), "r"((a)[1]), "r"((a)[2]), "r"((a)[3]), \
                   "r"((b)[0]), "r"((b)[1]))
#define CP_ASYNC16(dst, src) \
    asm volatile("cp.async.cg.shared.global [%0], [%1], 16;" \
                 :: "r"(dst), "l"(src) : "memory")
#define CP_COMMIT() asm volatile("cp.async.commit_group;" ::: "memory")

#define KT        32
#define ROW_H     40
#define TILE_H    (128 * ROW_H)          // halves (5120)
// 1-pass core: 2 tiles/stage (A, B), 3-stage ring
#define STAGE1_H  (2 * TILE_H)
#define SMEM1     (3 * STAGE1_H * 2)     // 61440 B  (x3 CTAs = 184320 <= 228K)
// 2-pass core: 3 tiles/stage (Ah, Al, B), 3-stage ring
#define STAGE2_H  (3 * TILE_H)
#define SMEM2     (3 * STAGE2_H * 2)     // 92160 B

__device__ __forceinline__ uint32_t packh(half a, half b) {
    __half2 t; t.x = a; t.y = b;
    return *reinterpret_cast<uint32_t*>(&t);
}
__device__ __forceinline__ void split1h(float v, half& h, half& l) {
    h = __float2half(v);
    l = __float2half(v - __half2float(h));
}

// ---------------------------------------------------------------------------
// Fused rounding pass: all six fp32 tensors -> fp16.
// ---------------------------------------------------------------------------
__global__ __launch_bounds__(256)
void round_all(const float4* __restrict__ x,  const float4* __restrict__ ce,
               const float4* __restrict__ Wq, const float4* __restrict__ Wk,
               const float4* __restrict__ Wv, const float4* __restrict__ Wo,
               uint2* __restrict__ x16,  uint2* __restrict__ ce16,
               uint2* __restrict__ Wq16, uint2* __restrict__ Wk16,
               uint2* __restrict__ Wv16, uint2* __restrict__ Wo16)
{
    const int b = blockIdx.x;
    const float4* in; uint2* o; int lb;
    if (b < 8192)       { in = x;  o = x16;  lb = b; }
    else if (b < 16384) { in = ce; o = ce16; lb = b - 8192; }
    else if (b < 17408) { in = Wq; o = Wq16; lb = b - 16384; }
    else if (b < 18432) { in = Wk; o = Wk16; lb = b - 17408; }
    else if (b < 19456) { in = Wv; o = Wv16; lb = b - 18432; }
    else                { in = Wo; o = Wo16; lb = b - 19456; }

    const int i = lb * 256 + threadIdx.x;
    float4 v = in[i];
    o[i] = make_uint2(packh(__float2half(v.x), __float2half(v.y)),
                      packh(__float2half(v.z), __float2half(v.w)));
}

// ---------------------------------------------------------------------------
// 1-pass mainloop: acc += A@B^T. 2 smem tiles/stage, 3-stage ring.
// ---------------------------------------------------------------------------
__device__ __forceinline__ void gemm_core1(
    const half* __restrict__ Ag, const half* __restrict__ Bg,
    int ldA, int ldB, int K, char* smem_raw, float acc[4][8][4])
{
    const uint32_t sm_base = smem_u32(smem_raw);
    const int tid  = threadIdx.x;
    const int lane = tid & 31;
    const int wid  = tid >> 5;

    const int warp_m = (wid & 1) * 64;
    const int warp_n = (wid >> 1) * 64;

    const int r0 = tid >> 2;
    const int kc = (tid & 3) * 8;

    const int arow  = warp_m + (lane & 15);
    const int acolr = (lane >> 4) << 3;
    const int brow_off = ((lane >> 4) << 3) + (lane & 7);
    const int bcolr = lane & 8;

    const int NK = K >> 5;

    auto load_stage = [&](int buf, int kt) {
        const uint32_t sbase = sm_base + (uint32_t)(buf * STAGE1_H) * 2;
        const int kk = kt * KT + kc;
#pragma unroll
        for (int rr = 0; rr < 4; rr++) {
            const int row = r0 + rr * 32;
            const uint32_t so = (uint32_t)(row * ROW_H + kc) * 2;
            CP_ASYNC16(sbase + so,                          Ag + (size_t)row * ldA + kk);
            CP_ASYNC16(sbase + (uint32_t)(TILE_H * 2) + so, Bg + (size_t)row * ldB + kk);
        }
    };

    load_stage(0, 0);
    CP_COMMIT();
    load_stage(1, 1);
    CP_COMMIT();

    for (int kt = 0; kt < NK; ++kt) {
        if (kt + 2 < NK) {
            load_stage((kt + 2) % 3, kt + 2);
            CP_COMMIT();
        }
        const int rem = NK - 1 - kt;
        if (rem >= 2)      asm volatile("cp.async.wait_group 2;" ::: "memory");
        else if (rem == 1) asm volatile("cp.async.wait_group 1;" ::: "memory");
        else               asm volatile("cp.async.wait_group 0;" ::: "memory");
        __syncthreads();

        const uint32_t stg = sm_base + (uint32_t)((kt % 3) * STAGE1_H) * 2;
#pragma unroll
        for (int half_ = 0; half_ < 2; ++half_) {
            const int kk = half_ * 16;
            uint32_t af[4][4];
            uint32_t bb[8][2];

#pragma unroll
            for (int i = 0; i < 4; i++) {
                const uint32_t byt = (uint32_t)(((arow + i * 16) * ROW_H + kk + acolr) * 2);
                LDMX4(af[i][0], af[i][1], af[i][2], af[i][3], stg + byt);
            }
#pragma unroll
            for (int jj = 0; jj < 8; jj += 2) {
                const uint32_t byt =
                    (uint32_t)(((warp_n + jj * 8 + brow_off) * ROW_H + kk + bcolr) * 2);
                LDMX4(bb[jj][0], bb[jj][1], bb[jj + 1][0], bb[jj + 1][1],
                      stg + (uint32_t)(TILE_H * 2) + byt);
            }
#pragma unroll
            for (int i = 0; i < 4; i++)
#pragma unroll
                for (int j = 0; j < 8; j++)
                    MMA16816(acc[i][j], af[i], bb[j]);
        }
        __syncthreads();
    }
}

// ---------------------------------------------------------------------------
// 2-pass mainloop (outproj): acc += (Ah+Al)@B^T. 3 tiles/stage, 3-stage ring.
// ---------------------------------------------------------------------------
__device__ __forceinline__ void gemm_core2(
    const half* __restrict__ Agh, const half* __restrict__ Agl,
    const half* __restrict__ Bg,
    int ldA, int ldB, int K, char* smem_raw, float acc[4][8][4])
{
    const uint32_t sm_base = smem_u32(smem_raw);
    const int tid  = threadIdx.x;
    const int lane = tid & 31;
    const int wid  = tid >> 5;

    const int warp_m = (wid & 1) * 64;
    const int warp_n = (wid >> 1) * 64;

    const int r0 = tid >> 2;
    const int kc = (tid & 3) * 8;

    const int arow  = warp_m + (lane & 15);
    const int acolr = (lane >> 4) << 3;
    const int brow_off = ((lane >> 4) << 3) + (lane & 7);
    const int bcolr = lane & 8;

    const int NK = K >> 5;

    auto load_stage = [&](int buf, int kt) {
        const uint32_t sbase = sm_base + (uint32_t)(buf * STAGE2_H) * 2;
        const int kk = kt * KT + kc;
#pragma unroll
        for (int rr = 0; rr < 4; rr++) {
            const int row = r0 + rr * 32;
            const uint32_t so = (uint32_t)(row * ROW_H + kc) * 2;
            CP_ASYNC16(sbase + so,                              Agh + (size_t)row * ldA + kk);
            CP_ASYNC16(sbase + (uint32_t)(TILE_H * 2) + so,     Agl + (size_t)row * ldA + kk);
            CP_ASYNC16(sbase + (uint32_t)(2 * TILE_H * 2) + so, Bg  + (size_t)row * ldB + kk);
        }
    };

    load_stage(0, 0);
    CP_COMMIT();
    load_stage(1, 1);
    CP_COMMIT();

    for (int kt = 0; kt < NK; ++kt) {
        if (kt + 2 < NK) {
            load_stage((kt + 2) % 3, kt + 2);
            CP_COMMIT();
        }
        const int rem = NK - 1 - kt;
        if (rem >= 2)      asm volatile("cp.async.wait_group 2;" ::: "memory");
        else if (rem == 1) asm volatile("cp.async.wait_group 1;" ::: "memory");
        else               asm volatile("cp.async.wait_group 0;" ::: "memory");
        __syncthreads();

        const uint32_t stg = sm_base + (uint32_t)((kt % 3) * STAGE2_H) * 2;
#pragma unroll
        for (int half_ = 0; half_ < 2; ++half_) {
            const int kk = half_ * 16;
            uint32_t af[4][4];
            uint32_t bb[8][2];

#pragma unroll
            for (int i = 0; i < 4; i++) {
                const uint32_t byt = (uint32_t)(((arow + i * 16) * ROW_H + kk + acolr) * 2);
                LDMX4(af[i][0], af[i][1], af[i][2], af[i][3], stg + byt);
            }
#pragma unroll
            for (int jj = 0; jj < 8; jj += 2) {
                const uint32_t byt =
                    (uint32_t)(((warp_n + jj * 8 + brow_off) * ROW_H + kk + bcolr) * 2);
                LDMX4(bb[jj][0], bb[jj][1], bb[jj + 1][0], bb[jj + 1][1],
                      stg + (uint32_t)(2 * TILE_H * 2) + byt);
            }
#pragma unroll
            for (int i = 0; i < 4; i++)
#pragma unroll
                for (int j = 0; j < 8; j++)
                    MMA16816(acc[i][j], af[i], bb[j]);

#pragma unroll
            for (int i = 0; i < 4; i++) {
                const uint32_t byt = (uint32_t)(((arow + i * 16) * ROW_H + kk + acolr) * 2);
                LDMX4(af[i][0], af[i][1], af[i][2], af[i][3],
                      stg + (uint32_t)(TILE_H * 2) + byt);
            }
#pragma unroll
            for (int i = 0; i < 4; i++)
#pragma unroll
                for (int j = 0; j < 8; j++)
                    MMA16816(acc[i][j], af[i], bb[j]);
        }
        __syncthreads();
    }
}

// ---------------------------------------------------------------------------
// Fused Q/K/V projection (1-pass, 3 CTAs/SM): grid (8, 64, 3).
// ---------------------------------------------------------------------------
__global__ __launch_bounds__(128, 3)
void gemm_qkv(const half* __restrict__ x16, const half* __restrict__ ce16,
              const half* __restrict__ Wq16, const half* __restrict__ Wk16,
              const half* __restrict__ Wv16,
              const float* __restrict__ bq, const float* __restrict__ bk,
              const float* __restrict__ bv,
              half* __restrict__ Q16, half* __restrict__ K16,
              half* __restrict__ Vt16)
{
    extern __shared__ __align__(16) char smem_raw[];
    const int z  = blockIdx.z;
    const int m0 = blockIdx.y * 128;
    const int n0 = blockIdx.x * 128;

    const half *A_, *B_;
    const float* bias;
    if (z == 0)      { A_ = x16;  B_ = Wq16; bias = bq; }
    else if (z == 1) { A_ = ce16; B_ = Wk16; bias = bk; }
    else             { A_ = ce16; B_ = Wv16; bias = bv; }

    float acc[4][8][4];
#pragma unroll
    for (int i = 0; i < 4; i++)
#pragma unroll
        for (int j = 0; j < 8; j++)
#pragma unroll
            for (int c = 0; c < 4; c++) acc[i][j][c] = 0.f;

    gemm_core1(A_ + (size_t)m0 * C_DIM, B_ + (size_t)n0 * C_DIM,
               C_DIM, C_DIM, C_DIM, smem_raw, acc);

    const int tid  = threadIdx.x;
    const int wid  = tid >> 5;
    const int lane = tid & 31;
    const int warp_m = (wid & 1) * 64;
    const int warp_n = (wid >> 1) * 64;
    const int gq = lane >> 2;
    const int tq = lane & 3;

#pragma unroll
    for (int i = 0; i < 4; i++) {
#pragma unroll
        for (int j = 0; j < 8; j++) {
            const int col = n0 + warp_n + j * 8 + tq * 2;
#pragma unroll
            for (int h = 0; h < 2; h++) {
                const int row = m0 + warp_m + i * 16 + gq + h * 8;
                float2 bb = *reinterpret_cast<const float2*>(bias + col);
                float v0 = acc[i][j][2 * h]     + bb.x;
                float v1 = acc[i][j][2 * h + 1] + bb.y;
                if (z == 0) {
                    *reinterpret_cast<uint32_t*>(Q16 + (size_t)row * C_DIM + col) =
                        packh(__float2half(v0), __float2half(v1));
                } else if (z == 1) {
                    *reinterpret_cast<uint32_t*>(K16 + (size_t)row * C_DIM + col) =
                        packh(__float2half(v0), __float2half(v1));
                } else {
                    Vt16[(size_t)col * M_ALL + row]       = __float2half(v0);
                    Vt16[(size_t)(col + 1) * M_ALL + row] = __float2half(v1);
                }
            }
        }
    }
}

// ---------------------------------------------------------------------------
// 1-pass generic GEMM (3 CTAs/SM). OUT_MODE: 0 fp32, 1 split fp16 hi/lo.
// ---------------------------------------------------------------------------
template<int OUT_MODE, bool HAS_RES>
__global__ __launch_bounds__(128, 3)
void gemm1(const half* __restrict__ Ag, const half* __restrict__ Bg,
           const float* __restrict__ Rm,
           float* __restrict__ Cf, half* __restrict__ Ch, half* __restrict__ Cl,
           int K, float alpha, int ldA, int ldB, int ldC,
           long long sA, long long sB, long long sC, long long sR)
{
    extern __shared__ __align__(16) char smem_raw[];
    const int z  = blockIdx.z;
    const int m0 = blockIdx.y * 128;
    const int n0 = blockIdx.x * 128;

    float acc[4][8][4];
#pragma unroll
    for (int i = 0; i < 4; i++)
#pragma unroll
        for (int j = 0; j < 8; j++)
#pragma unroll
            for (int c = 0; c < 4; c++) acc[i][j][c] = 0.f;

    gemm_core1(Ag + z * sA + (size_t)m0 * ldA, Bg + z * sB + (size_t)n0 * ldB,
               ldA, ldB, K, smem_raw, acc);

    const int tid  = threadIdx.x;
    const int wid  = tid >> 5;
    const int lane = tid & 31;
    const int warp_m = (wid & 1) * 64;
    const int warp_n = (wid >> 1) * 64;
    const int gq = lane >> 2;
    const int tq = lane & 3;

#pragma unroll
    for (int i = 0; i < 4; i++) {
#pragma unroll
        for (int j = 0; j < 8; j++) {
            const int col = n0 + warp_n + j * 8 + tq * 2;
#pragma unroll
            for (int h = 0; h < 2; h++) {
                const int row = m0 + warp_m + i * 16 + gq + h * 8;
                float v0 = acc[i][j][2 * h]     * alpha;
                float v1 = acc[i][j][2 * h + 1] * alpha;
                if (HAS_RES) {
                    float2 r = *reinterpret_cast<const float2*>(
                        Rm + z * sR + (size_t)row * ldC + col);
                    v0 += r.x; v1 += r.y;
                }
                if (OUT_MODE == 0) {
                    *reinterpret_cast<float2*>(Cf + z * sC + (size_t)row * ldC + col)
                        = make_float2(v0, v1);
                } else {
                    half h0, h1, l0, l1;
                    split1h(v0, h0, l0); split1h(v1, h1, l1);
                    const size_t idx = z * sC + (size_t)row * ldC + col;
                    *reinterpret_cast<uint32_t*>(Ch + idx) = packh(h0, h1);
                    *reinterpret_cast<uint32_t*>(Cl + idx) = packh(l0, l1);
                }
            }
        }
    }
}

// ---------------------------------------------------------------------------
// 2-pass out-projection (2 CTAs/SM): out = (Th+Tl)@Wo^T + bo (fp32 out).
// ---------------------------------------------------------------------------
__global__ __launch_bounds__(128, 2)
void gemm_out(const half* __restrict__ Th, const half* __restrict__ Tl,
              const half* __restrict__ Wo16,
              const float* __restrict__ bo, float* __restrict__ out)
{
    extern __shared__ __align__(16) char smem_raw[];
    const int m0 = blockIdx.y * 128;
    const int n0 = blockIdx.x * 128;

    float acc[4][8][4];
#pragma unroll
    for (int i = 0; i < 4; i++)
#pragma unroll
        for (int j = 0; j < 8; j++)
#pragma unroll
            for (int c = 0; c < 4; c++) acc[i][j][c] = 0.f;

    gemm_core2(Th + (size_t)m0 * C_DIM, Tl + (size_t)m0 * C_DIM,
               Wo16 + (size_t)n0 * C_DIM, C_DIM, C_DIM, C_DIM, smem_raw, acc);

    const int tid  = threadIdx.x;
    const int wid  = tid >> 5;
    const int lane = tid & 31;
    const int warp_m = (wid & 1) * 64;
    const int warp_n = (wid >> 1) * 64;
    const int gq = lane >> 2;
    const int tq = lane & 3;

#pragma unroll
    for (int i = 0; i < 4; i++) {
#pragma unroll
        for (int j = 0; j < 8; j++) {
            const int col = n0 + warp_n + j * 8 + tq * 2;
#pragma unroll
            for (int h = 0; h < 2; h++) {
                const int row = m0 + warp_m + i * 16 + gq + h * 8;
                float2 bb = *reinterpret_cast<const float2*>(bo + col);
                *reinterpret_cast<float2*>(out + (size_t)row * C_DIM + col) =
                    make_float2(acc[i][j][2 * h] + bb.x, acc[i][j][2 * h + 1] + bb.y);
            }
        }
    }
}

// ---------------------------------------------------------------------------
// Row softmax (2048/row) -> fp16 probabilities.
// ---------------------------------------------------------------------------
__global__ __launch_bounds__(256)
void softmax2048(const float* __restrict__ S, half* __restrict__ P)
{
    const long long row = blockIdx.x;
    const float* p = S + row * 2048;
    const int tid = threadIdx.x;
    const int w = tid >> 5, l = tid & 31;

    float v[8];
    {
        float4 x0 = *reinterpret_cast<const float4*>(p + tid * 8);
        float4 x1 = *reinterpret_cast<const float4*>(p + tid * 8 + 4);
        v[0] = x0.x; v[1] = x0.y; v[2] = x0.z; v[3] = x0.w;
        v[4] = x1.x; v[5] = x1.y; v[6] = x1.z; v[7] = x1.w;
    }
    __shared__ float smax[8], ssum[8];

    float m = v[0];
#pragma unroll
    for (int j = 1; j < 8; j++) m = fmaxf(m, v[j]);
#pragma unroll
    for (int off = 16; off >= 1; off >>= 1)
        m = fmaxf(m, __shfl_xor_sync(0xffffffffu, m, off));
    if (l == 0) smax[w] = m;
    __syncthreads();
    float bm = smax[0];
#pragma unroll
    for (int j = 1; j < 8; j++) bm = fmaxf(bm, smax[j]);

    float s = 0.f;
#pragma unroll
    for (int j = 0; j < 8; j++) { v[j] = expf(v[j] - bm); s += v[j]; }
#pragma unroll
    for (int off = 16; off >= 1; off >>= 1)
        s += __shfl_xor_sync(0xffffffffu, s, off);
    if (l == 0) ssum[w] = s;
    __syncthreads();
    float tot = ssum[0];
#pragma unroll
    for (int j = 1; j < 8; j++) tot += ssum[j];

    const float inv = 1.f / tot;
    half hh[8];
#pragma unroll
    for (int j = 0; j < 8; j++) hh[j] = __float2half(v[j] * inv);

    const long long ob = row * 2048 + tid * 8;
    *reinterpret_cast<uint2*>(P + ob) =
        make_uint2(packh(hh[0], hh[1]), packh(hh[2], hh[3]));
    *reinterpret_cast<uint2*>(P + ob + 4) =
        make_uint2(packh(hh[4], hh[5]), packh(hh[6], hh[7]));
}

// ---------------------------------------------------------------------------
extern "C" void kernel_launch(void* const* d_in, const int* in_sizes, int n_in,
                              void* d_out, int out_size)
{
    (void)in_sizes; (void)n_in; (void)out_size;
    const float* x  = (const float*)d_in[0];
    const float* ce = (const float*)d_in[1];
    const float* Wq = (const float*)d_in[2];
    const float* bq = (const float*)d_in[3];
    const float* Wk = (const float*)d_in[4];
    const float* bk = (const float*)d_in[5];
    const float* Wv = (const float*)d_in[6];
    const float* bv = (const float*)d_in[7];
    const float* Wo = (const float*)d_in[8];
    const float* bo = (const float*)d_in[9];
    float* out = (float*)d_out;

    float* S;
    half *x16, *ce16, *Wq16, *Wk16, *Wv16, *Wo16;
    half *Q16, *K16, *Vt16, *P16, *Th, *Tl;
    cudaGetSymbolAddress((void**)&S,    g_S);
    cudaGetSymbolAddress((void**)&x16,  g_x16);  cudaGetSymbolAddress((void**)&ce16, g_ce16);
    cudaGetSymbolAddress((void**)&Wq16, g_Wq16); cudaGetSymbolAddress((void**)&Wk16, g_Wk16);
    cudaGetSymbolAddress((void**)&Wv16, g_Wv16); cudaGetSymbolAddress((void**)&Wo16, g_Wo16);
    cudaGetSymbolAddress((void**)&Q16,  g_Q16);  cudaGetSymbolAddress((void**)&K16,  g_K16);
    cudaGetSymbolAddress((void**)&Vt16, g_Vt16); cudaGetSymbolAddress((void**)&P16,  g_P16);
    cudaGetSymbolAddress((void**)&Th,   g_Th);   cudaGetSymbolAddress((void**)&Tl,   g_Tl);

    cudaFuncSetAttribute(gemm_qkv, cudaFuncAttributeMaxDynamicSharedMemorySize, SMEM1);
    cudaFuncSetAttribute(gemm1<0, false>, cudaFuncAttributeMaxDynamicSharedMemorySize, SMEM1);
    cudaFuncSetAttribute(gemm1<1, true >, cudaFuncAttributeMaxDynamicSharedMemorySize, SMEM1);
    cudaFuncSetAttribute(gemm_out, cudaFuncAttributeMaxDynamicSharedMemorySize, SMEM2);

    // fused rounding pass
    round_all<<<20480, 256>>>(
        (const float4*)x, (const float4*)ce, (const float4*)Wq,
        (const float4*)Wk, (const float4*)Wv, (const float4*)Wo,
        (uint2*)x16, (uint2*)ce16, (uint2*)Wq16, (uint2*)Wk16,
        (uint2*)Wv16, (uint2*)Wo16);

    const long long sQ = (long long)S_DIM * C_DIM;
    const long long sS = (long long)S_DIM * S_DIM;

    // fused Q/K/V projections (one launch, 1536 CTAs, 1-pass)
    gemm_qkv<<<dim3(8, 64, 3), 128, SMEM1>>>(
        x16, ce16, Wq16, Wk16, Wv16, bq, bk, bv, Q16, K16, Vt16);

    // scores: per-batch Q @ K^T / 32 -> fp32 S (1-pass)
    gemm1<0, false><<<dim3(16, 16, B_DIM), 128, SMEM1>>>(
        Q16, K16, nullptr, S, nullptr, nullptr,
        C_DIM, 0.03125f, C_DIM, C_DIM, S_DIM, sQ, sQ, sS, 0);

    softmax2048<<<M_ALL, 256>>>(S, P16);

    // attended + residual -> split fp16 T (1-pass)
    gemm1<1, true><<<dim3(8, 16, B_DIM), 128, SMEM1>>>(
        P16, Vt16, x, nullptr, Th, Tl,
        S_DIM, 1.f, S_DIM, M_ALL, C_DIM, sS, S_DIM, sQ, sQ);

    // output projection (2-pass: T split, Wo rounded; fp32 out)
    gemm_out<<<dim3(8, 64, 1), 128, SMEM2>>>(Th, Tl, Wo16, bo, out);
}